// round 13
// baseline (speedup 1.0000x reference)
#include <cuda_runtime.h>
#include <cuda_fp16.h>
#include <cstdint>

// ---------------------------------------------------------------------------
// SimpleRNN: logits = W_out( scan_tanh( W_ih·emb[x] + b_ih , W_hh, b_hh ) ) + b_out
// B=8, S=2048, E=256, H=512, V=16000
// Round 12: (a) scan back to ONE __syncthreads/step (R6 exact);
// (b) xproj folded into worker tickets (fp16 mma, gather-A), scan waits on
// per-chunk xproj flags; (c) serial xproj SGEMM launch removed.
// ---------------------------------------------------------------------------

#define B_  8
#define S_  2048
#define E_  256
#define H_  512
#define V_  16000
#define MTOT (B_ * S_)                      // 16384
static const long long VOUT = (long long)B_ * S_ * V_;   // 262,144,000

// Scratch (device globals: no allocation allowed)
__device__ float  g_xproj[(size_t)MTOT * H_];    // 33.5 MB
__device__ __half g_h16  [(size_t)MTOT * H_];    // 16.8 MB
__device__ __half g_w16  [(size_t)V_  * H_];     // 16.4 MB
__device__ __half g_e16  [(size_t)V_  * E_];     // 8.2 MB
__device__ __half g_wih16[(size_t)H_  * E_];     // 0.26 MB
__device__ float  g_dummy_hf[B_ * H_];
__device__ unsigned int g_progress[B_][8];       // scan chunks done (count 8)
__device__ unsigned int g_xpready [B_][8];       // xproj n-tiles done (count 4)
__device__ unsigned int g_ticket;

#define NT_XPROJ 256                // 8 chunks * 8 batches * 4 n-tiles
#define NT_TOTAL (NT_XPROJ + 8000)  // + 8 chunks * 8 batches * 125 n-tiles

// ---------------- small PTX helpers -----------------------------------------
__device__ __forceinline__ void ffma2(unsigned long long& acc,
                                      unsigned long long a,
                                      unsigned long long b) {
    asm("fma.rn.f32x2 %0, %1, %2, %0;" : "+l"(acc) : "l"(a), "l"(b));
}
__device__ __forceinline__ void unpack2(unsigned long long v, float& lo, float& hi) {
    asm("mov.b64 {%0, %1}, %2;" : "=f"(lo), "=f"(hi) : "l"(v));
}
__device__ __forceinline__ uint32_t smem_u32(const void* p) {
    uint32_t a;
    asm("{ .reg .u64 t; cvta.to.shared.u64 t, %1; cvt.u32.u64 %0, t; }"
        : "=r"(a) : "l"(p));
    return a;
}
__device__ __forceinline__ void cp_async16(uint32_t saddr, const void* gaddr) {
    asm volatile("cp.async.cg.shared.global [%0], [%1], 16;"
                 :: "r"(saddr), "l"(gaddr));
}
#define CP_COMMIT() asm volatile("cp.async.commit_group;" ::: "memory")
template <int N>
__device__ __forceinline__ void cp_wait() {
    asm volatile("cp.async.wait_group %0;" :: "n"(N) : "memory");
}
__device__ __forceinline__ void ldsm4(uint32_t addr, uint32_t& r0, uint32_t& r1,
                                      uint32_t& r2, uint32_t& r3) {
    asm volatile("ldmatrix.sync.aligned.m8n8.x4.shared.b16 {%0,%1,%2,%3}, [%4];"
                 : "=r"(r0), "=r"(r1), "=r"(r2), "=r"(r3) : "r"(addr));
}
__device__ __forceinline__ void mma_f16(float* d,
                                        uint32_t a0, uint32_t a1,
                                        uint32_t a2, uint32_t a3,
                                        uint32_t b0, uint32_t b1) {
    asm volatile("mma.sync.aligned.m16n8k16.row.col.f32.f16.f16.f32 "
                 "{%0,%1,%2,%3}, {%4,%5,%6,%7}, {%8,%9}, {%0,%1,%2,%3};"
                 : "+f"(d[0]), "+f"(d[1]), "+f"(d[2]), "+f"(d[3])
                 : "r"(a0), "r"(a1), "r"(a2), "r"(a3), "r"(b0), "r"(b1));
}
__device__ __forceinline__ void spin_ge(const unsigned int* p, unsigned int n) {
    unsigned int v;
    for (;;) {
        asm volatile("ld.acquire.gpu.global.u32 %0, [%1];"
                     : "=r"(v) : "l"(p) : "memory");
        if (v >= n) break;
        __nanosleep(256);
    }
}
__device__ __forceinline__ void rel_add1(unsigned int* p) {
    asm volatile("red.release.gpu.global.add.u32 [%0], %1;"
                 :: "l"(p), "r"(1u) : "memory");
}

// ---------------------------------------------------------------------------
// Kernel 0: fp32 -> fp16 conversion
// ---------------------------------------------------------------------------
__global__ void to_half(const float* __restrict__ src,
                        __half* __restrict__ dst, int n)
{
    int i = blockIdx.x * blockDim.x + threadIdx.x;
    int stride = gridDim.x * blockDim.x;
    for (; i < n; i += stride) dst[i] = __float2half(src[i]);
}

// ---------------------------------------------------------------------------
// Kernel 0b: zero flags + ticket (re-run every graph replay)
// ---------------------------------------------------------------------------
__global__ void zero_flags()
{
    int t = threadIdx.x;
    if (t < 64)             ((unsigned int*)g_progress)[t]      = 0u;
    else if (t < 128)       ((unsigned int*)g_xpready)[t - 64]  = 0u;
    else if (t == 128)      g_ticket = 0u;
}

// ---------------------------------------------------------------------------
// Fused kernel: 136 CTAs x 512 thr, cluster 8 (17 clusters — all wave-1).
// Blocks 0..63  : scan (cluster = batch), exact R6-measured body (ONE
//                 syncthreads/step), waits on xproj flags per 256-step chunk.
// Blocks 64..135: persistent GEMM workers. Tickets 0..255 = xproj tiles
//                 (256Mx128N, K=256, gather-A, no deps); 256.. = logits tiles
//                 (256Mx128N, K=512, wait on scan progress).
// Scan CTAs fall into the worker loop when done (drain on 136 SMs).
// ---------------------------------------------------------------------------
#define OP_PITCH   144
#define W_STAGE    55296
#define W_BOFF     36864          // B region offset within stage (256*144)
#define FUSED_SMEM (2 * W_STAGE)  // 110592

__global__ __launch_bounds__(512, 1) __cluster_dims__(8, 1, 1)
void fused_all(const int*   __restrict__ xi,
               const float* __restrict__ hidden0,
               const float* __restrict__ W_hh,
               const float* __restrict__ b_hh,
               const float* __restrict__ b_ih,
               __half* __restrict__ h16,
               float*  __restrict__ xp,
               float*  __restrict__ hfinal,
               const __half* __restrict__ emb16,
               const __half* __restrict__ wih16,
               const __half* __restrict__ Bw,
               const float* __restrict__ bias,
               float* __restrict__ C)
{
    extern __shared__ char dsm[];
    __shared__ int sh_tile;
    const int tid = threadIdx.x;

    if (blockIdx.x < 64) {
        // =================== SCAN ROLE (R6-measured body) ===================
        float* h_buf = (float*)dsm;                  // [2][512]
        float* part  = (float*)(dsm + 4096);         // [8][64]

        const int batch = blockIdx.x >> 3;
        const int rank  = blockIdx.x & 7;
        const int out   = tid & 63;
        const int kc    = tid >> 6;
        const int kbase = kc * 64;
        const int grow  = rank * 64 + out;

        unsigned long long w2[32];
        {
            const unsigned long long* wq =
                (const unsigned long long*)(W_hh + (size_t)grow * H_ + kbase);
            #pragma unroll
            for (int j = 0; j < 32; j++) w2[j] = wq[j];
        }

        h_buf[tid] = hidden0[batch * H_ + tid];
        const float bhh = (tid < 64) ? b_hh[rank * 64 + tid] : 0.f;
        __syncthreads();
        asm volatile("barrier.cluster.arrive.aligned;" ::: "memory");
        asm volatile("barrier.cluster.wait.aligned;"   ::: "memory");

        const float* xp_b = xp  + (size_t)batch * S_ * H_ + rank * 64;
        __half*      hh_b = h16 + (size_t)batch * S_ * H_ + rank * 64;

        float hn = 0.f;
        for (int t = 0; t < S_; t++) {
            // wait for this 256-step chunk's xproj tiles (workers produce them)
            if ((t & 255) == 0) {
                if (tid == 0) spin_ge(&g_xpready[batch][t >> 8], 4u);
                __syncthreads();
            }
            const int pb = t & 1;

            float xpv = 0.f;
            if (tid < 64) xpv = xp_b[(size_t)t * H_ + tid];

            const unsigned long long* hq =
                (const unsigned long long*)&h_buf[pb * H_ + kbase];
            unsigned long long a0 = 0ull, a1 = 0ull;
            #pragma unroll
            for (int j = 0; j < 16; j++) {
                ffma2(a0, w2[2 * j],     hq[2 * j]);
                ffma2(a1, w2[2 * j + 1], hq[2 * j + 1]);
            }
            float l0, hi0, l1, hi1;
            unpack2(a0, l0, hi0);
            unpack2(a1, l1, hi1);
            part[kc * 64 + out] = (l0 + hi0) + (l1 + hi1);
            __syncthreads();                   // the ONE per-step syncthreads

            if (tid < 64) {
                float s = xpv + bhh;
                #pragma unroll
                for (int c = 0; c < 8; c++) s += part[c * 64 + tid];
                hn = tanhf(s);
                hh_b[(size_t)t * H_ + tid] = __float2half(hn);

                uint32_t laddr = smem_u32(&h_buf[(pb ^ 1) * H_ + grow]);
                #pragma unroll
                for (int pr = 0; pr < 8; pr++) {
                    uint32_t paddr;
                    asm("mapa.shared::cluster.u32 %0, %1, %2;"
                        : "=r"(paddr) : "r"(laddr), "r"(pr));
                    asm volatile("st.shared::cluster.f32 [%0], %1;"
                                 :: "r"(paddr), "f"(hn) : "memory");
                }
            }
            // arrive releases our DSMEM stores + part reads; wait acquires
            asm volatile("barrier.cluster.arrive.aligned;" ::: "memory");
            asm volatile("barrier.cluster.wait.aligned;"   ::: "memory");

            if (((t & 255) == 255) && tid == 0)
                rel_add1(&g_progress[batch][t >> 8]);
        }
        if (tid < 64) hfinal[batch * H_ + grow] = hn;
        __syncthreads();   // done with scan smem; fall into worker loop
    }

    // ====================== WORKER ROLE (all CTAs) ==========================
    const __half* Ah = h16;
    const uint32_t sbase = smem_u32(dsm);
    const int warp = tid >> 5, lane = tid & 31;
    const int wm = warp & 7;                 // 0..7 (M)
    const int wn = warp >> 3;                // 0..1 (N)

    const int arow = wm * 32 + (lane & 15);
    const int aoff = (lane >> 4) * 16;
    const int nrow = wn * 64 + (lane & 7) + ((lane >> 4) & 1) * 8;
    const int boff = ((lane >> 3) & 1) * 16;

    for (;;) {
        if (tid == 0) sh_tile = (int)atomicAdd(&g_ticket, 1u);
        __syncthreads();
        const int tile = sh_tile;
        if (tile >= NT_TOTAL) break;

        const bool isx = (tile < NT_XPROJ);
        int mblk, nblk, nkc, fb, fc;
        if (isx) {
            fc = tile >> 5;                  // chunk-major: all batches of c=0 first
            fb = (tile >> 2) & 7;
            const int nt = tile & 3;
            mblk = fb * S_ + fc * 256;
            nblk = nt * 128;
            nkc  = 4;                         // K = 256
        } else {
            const int t2  = tile - NT_XPROJ;
            fc = t2 / 1000;
            const int rem = t2 - fc * 1000;
            fb = rem / 125;
            const int nt  = rem - fb * 125;
            mblk = fb * S_ + fc * 256;
            nblk = nt * 128;
            nkc  = 8;                         // K = 512
            if (tid == 0) spin_ge(&g_progress[fb][fc], 8u);
            __syncthreads();
        }

        auto wload = [&](int kc, int st) {
            const uint32_t sst = sbase + (uint32_t)st * W_STAGE;
            #pragma unroll
            for (int j = 0; j < 6; j++) {
                int u = tid + 512 * j;
                if (u < 2048) {               // A: 256 rows x 8 chunks
                    int row = u >> 3, cc = u & 7;
                    const char* ga;
                    if (isx) {
                        int ix = __ldg(xi + mblk + row);
                        ga = (const char*)emb16 +
                             (size_t)ix * (E_ * 2) + kc * 128 + cc * 16;
                    } else {
                        ga = (const char*)Ah +
                             (size_t)(mblk + row) * (H_ * 2) + kc * 128 + cc * 16;
                    }
                    cp_async16(sst + row * OP_PITCH + cc * 16, ga);
                } else {                      // B: 128 rows x 8 chunks
                    int v2 = u - 2048;
                    int row = v2 >> 3, cc = v2 & 7;
                    const char* gb = isx
                        ? (const char*)wih16 +
                          (size_t)(nblk + row) * (E_ * 2) + kc * 128 + cc * 16
                        : (const char*)Bw +
                          (size_t)(nblk + row) * (H_ * 2) + kc * 128 + cc * 16;
                    cp_async16(sst + W_BOFF + row * OP_PITCH + cc * 16, gb);
                }
            }
            CP_COMMIT();
        };

        float acc[2][8][4];
        #pragma unroll
        for (int mi = 0; mi < 2; mi++)
            #pragma unroll
            for (int ni = 0; ni < 8; ni++)
                #pragma unroll
                for (int q = 0; q < 4; q++) acc[mi][ni][q] = 0.f;

        wload(0, 0);
        wload(1, 1);

        #pragma unroll 1
        for (int kc = 0; kc < nkc; kc++) {
            const int cur = kc & 1;
            if (kc + 1 < nkc) cp_wait<1>(); else cp_wait<0>();
            __syncthreads();

            const uint32_t sst = sbase + (uint32_t)cur * W_STAGE;
            const uint32_t ahb = sst;
            const uint32_t bwb = sst + W_BOFF;

            #pragma unroll
            for (int ks = 0; ks < 4; ks++) {
                const int kb = ks * 32;
                uint32_t ah[2][4];
                #pragma unroll
                for (int mi = 0; mi < 2; mi++)
                    ldsm4(ahb + (arow + mi * 16) * OP_PITCH + kb + aoff,
                          ah[mi][0], ah[mi][1], ah[mi][2], ah[mi][3]);
                #pragma unroll
                for (int g = 0; g < 4; g++) {
                    uint32_t bh[4];
                    ldsm4(bwb + (nrow + g * 16) * OP_PITCH + kb + boff,
                          bh[0], bh[1], bh[2], bh[3]);
                    #pragma unroll
                    for (int mi = 0; mi < 2; mi++) {
                        mma_f16(acc[mi][2 * g],
                                ah[mi][0], ah[mi][1], ah[mi][2], ah[mi][3],
                                bh[0], bh[1]);
                        mma_f16(acc[mi][2 * g + 1],
                                ah[mi][0], ah[mi][1], ah[mi][2], ah[mi][3],
                                bh[2], bh[3]);
                    }
                }
            }
            __syncthreads();
            if (kc + 2 < nkc) wload(kc + 2, cur);
        }

        // epilogue
        const int rg = mblk + wm * 32 + (lane >> 2);
        const int cg = nblk + wn * 64 + (lane & 3) * 2;
        if (isx) {
            #pragma unroll
            for (int mi = 0; mi < 2; mi++) {
                #pragma unroll
                for (int ni = 0; ni < 8; ni++) {
                    const int row = rg + mi * 16;
                    const int col = cg + ni * 8;
                    const float b0 = __ldg(b_ih + col);
                    const float b1 = __ldg(b_ih + col + 1);
                    float2 v0 = make_float2(acc[mi][ni][0] + b0,
                                            acc[mi][ni][1] + b1);
                    float2 v1 = make_float2(acc[mi][ni][2] + b0,
                                            acc[mi][ni][3] + b1);
                    *(float2*)(xp + (size_t)row * H_ + col)       = v0;
                    *(float2*)(xp + (size_t)(row + 8) * H_ + col) = v1;
                }
            }
            __syncthreads();                  // all stores done (CTA)
            if (tid == 0) rel_add1(&g_xpready[fb][fc]);
        } else {
            #pragma unroll
            for (int mi = 0; mi < 2; mi++) {
                #pragma unroll
                for (int ni = 0; ni < 8; ni++) {
                    const int row = rg + mi * 16;
                    const int col = cg + ni * 8;
                    const float b0 = __ldg(bias + col);
                    const float b1 = __ldg(bias + col + 1);
                    float2 v0 = make_float2(acc[mi][ni][0] + b0,
                                            acc[mi][ni][1] + b1);
                    float2 v1 = make_float2(acc[mi][ni][2] + b0,
                                            acc[mi][ni][3] + b1);
                    *(float2*)(C + (size_t)row * V_ + col)       = v0;
                    *(float2*)(C + (size_t)(row + 8) * V_ + col) = v1;
                }
            }
            __syncthreads();                  // tile done before smem reuse
        }
    }
}

// ---------------------------------------------------------------------------
// Launch
// inputs: 0=x(i32)[B,S] 1=hidden[B,H] 2=embedding[V,E] 3=W_ih[H,E]
//         4=W_hh[H,H] 5=b_ih[H] 6=b_hh[H] 7=W_out[V,H] 8=b_out[V]
// output: logits [B,S,V] then h_final [B,H]
// ---------------------------------------------------------------------------
extern "C" void kernel_launch(void* const* d_in, const int* in_sizes, int n_in,
                              void* d_out, int out_size)
{
    const int*   x         = (const int*)  d_in[0];
    const float* hidden    = (const float*)d_in[1];
    const float* embedding = (const float*)d_in[2];
    const float* W_ih      = (const float*)d_in[3];
    const float* W_hh      = (const float*)d_in[4];
    const float* b_ih      = (const float*)d_in[5];
    const float* b_hh      = (const float*)d_in[6];
    const float* W_out     = (const float*)d_in[7];
    const float* b_out     = (const float*)d_in[8];
    float* out = (float*)d_out;

    float *xproj, *dummy;
    __half *h16, *w16, *e16, *wih16;
    cudaGetSymbolAddress((void**)&xproj, g_xproj);
    cudaGetSymbolAddress((void**)&h16,   g_h16);
    cudaGetSymbolAddress((void**)&w16,   g_w16);
    cudaGetSymbolAddress((void**)&e16,   g_e16);
    cudaGetSymbolAddress((void**)&wih16, g_wih16);
    cudaGetSymbolAddress((void**)&dummy, g_dummy_hf);

    float* hfin = ((long long)out_size >= VOUT + (long long)B_ * H_)
                      ? (out + VOUT) : dummy;

    static bool attr_done = false;
    if (!attr_done) {
        cudaFuncSetAttribute(fused_all,
                             cudaFuncAttributeMaxDynamicSharedMemorySize,
                             FUSED_SMEM);
        attr_done = true;
    }

    // 0) fp16 conversions + flag reset
    to_half<<<2048, 256>>>(W_out, w16, V_ * H_);
    to_half<<<1024, 256>>>(embedding, e16, V_ * E_);
    to_half<<<128, 256>>>(W_ih, wih16, H_ * E_);
    zero_flags<<<1, 160>>>();

    // 1) fused: xproj (workers) + scan (64 CTAs) + logits GEMM (overlap+drain)
    fused_all<<<136, 512, FUSED_SMEM>>>(
        x, hidden, W_hh, b_hh, b_ih, h16, xproj, hfin,
        e16, wih16, w16, b_out, out);
}

// round 14
// speedup vs baseline: 1.0947x; 1.0947x over previous
#include <cuda_runtime.h>
#include <cuda_fp16.h>
#include <cstdint>

// ---------------------------------------------------------------------------
// SimpleRNN: logits = W_out( scan_tanh( W_ih·emb[x] + b_ih , W_hh, b_hh ) ) + b_out
// B=8, S=2048, E=256, H=512, V=16000
// Round 13: exact R12 winner (2581.5us) with ONE change — the scan's second
// per-step __syncthreads removed (R6-proven single-sync structure).
// fp16-xproj fold reverted (it cost time AND doubled rel_err in R13).
// ---------------------------------------------------------------------------

#define B_  8
#define S_  2048
#define E_  256
#define H_  512
#define V_  16000
#define MTOT (B_ * S_)                      // 16384
static const long long VOUT = (long long)B_ * S_ * V_;   // 262,144,000

// Scratch (device globals: no allocation allowed)
__device__ float  g_xproj[(size_t)MTOT * H_];    // 33.5 MB
__device__ __half g_h16  [(size_t)MTOT * H_];    // 16.8 MB
__device__ __half g_w16  [(size_t)V_  * H_];     // 16.4 MB
__device__ float  g_dummy_hf[B_ * H_];
__device__ unsigned int g_progress[B_][8];       // per (batch, 256-step chunk)
__device__ unsigned int g_ticket;

// ---------------- small PTX helpers -----------------------------------------
__device__ __forceinline__ void ffma2(unsigned long long& acc,
                                      unsigned long long a,
                                      unsigned long long b) {
    asm("fma.rn.f32x2 %0, %1, %2, %0;" : "+l"(acc) : "l"(a), "l"(b));
}
__device__ __forceinline__ unsigned long long pack2(float x, float y) {
    unsigned long long r;
    asm("mov.b64 %0, {%1, %2};" : "=l"(r) : "f"(x), "f"(y));
    return r;
}
__device__ __forceinline__ void unpack2(unsigned long long v, float& lo, float& hi) {
    asm("mov.b64 {%0, %1}, %2;" : "=f"(lo), "=f"(hi) : "l"(v));
}
__device__ __forceinline__ uint32_t smem_u32(const void* p) {
    uint32_t a;
    asm("{ .reg .u64 t; cvta.to.shared.u64 t, %1; cvt.u32.u64 %0, t; }"
        : "=r"(a) : "l"(p));
    return a;
}
__device__ __forceinline__ void cp_async16(uint32_t saddr, const void* gaddr) {
    asm volatile("cp.async.cg.shared.global [%0], [%1], 16;"
                 :: "r"(saddr), "l"(gaddr));
}
#define CP_COMMIT() asm volatile("cp.async.commit_group;" ::: "memory")
template <int N>
__device__ __forceinline__ void cp_wait() {
    asm volatile("cp.async.wait_group %0;" :: "n"(N) : "memory");
}
__device__ __forceinline__ void ldsm4(uint32_t addr, uint32_t& r0, uint32_t& r1,
                                      uint32_t& r2, uint32_t& r3) {
    asm volatile("ldmatrix.sync.aligned.m8n8.x4.shared.b16 {%0,%1,%2,%3}, [%4];"
                 : "=r"(r0), "=r"(r1), "=r"(r2), "=r"(r3) : "r"(addr));
}
__device__ __forceinline__ void mma_f16(float* d,
                                        uint32_t a0, uint32_t a1,
                                        uint32_t a2, uint32_t a3,
                                        uint32_t b0, uint32_t b1) {
    asm volatile("mma.sync.aligned.m16n8k16.row.col.f32.f16.f16.f32 "
                 "{%0,%1,%2,%3}, {%4,%5,%6,%7}, {%8,%9}, {%0,%1,%2,%3};"
                 : "+f"(d[0]), "+f"(d[1]), "+f"(d[2]), "+f"(d[3])
                 : "r"(a0), "r"(a1), "r"(a2), "r"(a3), "r"(b0), "r"(b1));
}

// ---------------------------------------------------------------------------
// Kernel 0: W_out fp32 -> fp16
// ---------------------------------------------------------------------------
__global__ void to_half(const float* __restrict__ src,
                        __half* __restrict__ dst, int n)
{
    int i = blockIdx.x * blockDim.x + threadIdx.x;
    int stride = gridDim.x * blockDim.x;
    for (; i < n; i += stride) dst[i] = __float2half(src[i]);
}

// ---------------------------------------------------------------------------
// Kernel 0b: zero progress flags + ticket (re-run every graph replay)
// ---------------------------------------------------------------------------
__global__ void zero_flags()
{
    int t = threadIdx.x;
    if (t < 64) ((unsigned int*)g_progress)[t] = 0u;
    if (t == 64) g_ticket = 0u;
}

// ---------------------------------------------------------------------------
// Kernel 1: x_proj SGEMM (fp32, proven ~123us)
// ---------------------------------------------------------------------------
template <bool GATHER>
__global__ __launch_bounds__(256, 2)
void gemm_nt(const float* __restrict__ A, const float* __restrict__ Bmat,
             const float* __restrict__ bias, float* __restrict__ C,
             const int* __restrict__ idx, int M, int N, int K)
{
    __shared__ float As[2][8][128];
    __shared__ float Bs[2][8][128];

    const int tid  = threadIdx.x;
    const int mblk = blockIdx.y * 128;
    const int nblk = blockIdx.x * 128;

    const int arow = tid >> 1;
    const int kq   = (tid & 1) * 4;

    const float* Aptr;
    if (GATHER) Aptr = A + (size_t)idx[mblk + arow] * K;
    else        Aptr = A + (size_t)(mblk + arow) * K;
    const float* Bptr = Bmat + (size_t)(nblk + arow) * K;

    const int ty = tid >> 4;
    const int tx = tid & 15;

    unsigned long long acc2[8][4];
    #pragma unroll
    for (int i = 0; i < 8; i++)
        #pragma unroll
        for (int p = 0; p < 4; p++) acc2[i][p] = 0ull;

    {
        float4 a4 = *(const float4*)(Aptr + kq);
        float4 b4 = *(const float4*)(Bptr + kq);
        #pragma unroll
        for (int i = 0; i < 4; i++) {
            As[0][kq + i][arow] = ((const float*)&a4)[i];
            Bs[0][kq + i][arow] = ((const float*)&b4)[i];
        }
    }
    __syncthreads();

    const int nkt = K >> 3;
    for (int kt = 0; kt < nkt; kt++) {
        const int cur = kt & 1, nxt = cur ^ 1;
        float4 a4n, b4n;
        const bool more = (kt + 1 < nkt);
        if (more) {
            a4n = *(const float4*)(Aptr + (kt + 1) * 8 + kq);
            b4n = *(const float4*)(Bptr + (kt + 1) * 8 + kq);
        }
        #pragma unroll
        for (int k = 0; k < 8; k++) {
            float af[8];
            *(float4*)&af[0] = *(const float4*)&As[cur][k][ty * 8];
            *(float4*)&af[4] = *(const float4*)&As[cur][k][ty * 8 + 4];
            unsigned long long bp[4];
            const unsigned long long* bq =
                (const unsigned long long*)&Bs[cur][k][tx * 8];
            #pragma unroll
            for (int p = 0; p < 4; p++) bp[p] = bq[p];
            #pragma unroll
            for (int i = 0; i < 8; i++) {
                unsigned long long ad = pack2(af[i], af[i]);
                #pragma unroll
                for (int p = 0; p < 4; p++) ffma2(acc2[i][p], ad, bp[p]);
            }
        }
        if (more) {
            #pragma unroll
            for (int i = 0; i < 4; i++) {
                As[nxt][kq + i][arow] = ((const float*)&a4n)[i];
                Bs[nxt][kq + i][arow] = ((const float*)&b4n)[i];
            }
        }
        __syncthreads();
    }

    float bv[8];
    #pragma unroll
    for (int j = 0; j < 8; j++) bv[j] = bias[nblk + tx * 8 + j];

    #pragma unroll
    for (int i = 0; i < 8; i++) {
        size_t row = (size_t)(mblk + ty * 8 + i);
        float* cp = C + row * (size_t)N + nblk + tx * 8;
        float v[8];
        #pragma unroll
        for (int p = 0; p < 4; p++) {
            float lo, hi;
            unpack2(acc2[i][p], lo, hi);
            v[2 * p]     = lo + bv[2 * p];
            v[2 * p + 1] = hi + bv[2 * p + 1];
        }
        *(float4*)cp       = make_float4(v[0], v[1], v[2], v[3]);
        *(float4*)(cp + 4) = make_float4(v[4], v[5], v[6], v[7]);
    }
}

// ---------------------------------------------------------------------------
// Fused kernel: 136 CTAs x 512 thr, cluster 8 (17 clusters — all wave-1).
// Blocks 0..63  : scan (cluster = batch), R6 structure: part-write -> ONE
//                 __syncthreads -> producer tanh/stores -> cluster arrive/wait.
// Blocks 64..135: persistent GEMM workers (ticket + progress spin).
// Scan CTAs fall into the worker loop after finishing (drain on 136 SMs).
// GEMM tile: 256M x 128N, 16 warps (8M x 2N), K-chunk 64, 2-stage cp.async.
// ---------------------------------------------------------------------------
#define OP_PITCH   144
#define W_STAGE    55296
#define W_BOFF     36864          // B region offset within stage (256*144)
#define FUSED_SMEM (2 * W_STAGE)  // 110592
#define NTILES     8000           // 8 chunks * 8 batches * 125 n-tiles

__global__ __launch_bounds__(512, 1) __cluster_dims__(8, 1, 1)
void fused_scan_logits(const float* __restrict__ xproj,
                       const float* __restrict__ hidden0,
                       const float* __restrict__ W_hh,
                       const float* __restrict__ b_hh,
                       __half* __restrict__ h16,
                       float* __restrict__ hfinal,
                       const __half* __restrict__ Bw,
                       const float* __restrict__ bias,
                       float* __restrict__ C)
{
    extern __shared__ char dsm[];
    __shared__ int sh_tile;
    const int tid = threadIdx.x;

    if (blockIdx.x < 64) {
        // =================== SCAN ROLE (R6 single-sync body) ================
        float* h_buf = (float*)dsm;                  // [2][512]
        float* part  = (float*)(dsm + 4096);         // [8][64]

        const int batch = blockIdx.x >> 3;
        const int rank  = blockIdx.x & 7;
        const int out   = tid & 63;
        const int kc    = tid >> 6;
        const int kbase = kc * 64;
        const int grow  = rank * 64 + out;

        unsigned long long w2[32];
        {
            const unsigned long long* wq =
                (const unsigned long long*)(W_hh + (size_t)grow * H_ + kbase);
            #pragma unroll
            for (int j = 0; j < 32; j++) w2[j] = wq[j];
        }

        h_buf[tid] = hidden0[batch * H_ + tid];      // h_buf[0][tid]
        const float bhh = (tid < 64) ? b_hh[rank * 64 + tid] : 0.f;
        __syncthreads();
        asm volatile("barrier.cluster.arrive.aligned;" ::: "memory");
        asm volatile("barrier.cluster.wait.aligned;"   ::: "memory");

        const float* xp_b = xproj + (size_t)batch * S_ * H_ + rank * 64;
        __half*      hh_b = h16   + (size_t)batch * S_ * H_ + rank * 64;

        float hn = 0.f;
        for (int t = 0; t < S_; t++) {
            const int pb = t & 1;

            float xp = 0.f;
            if (tid < 64) xp = xp_b[(size_t)t * H_ + tid];

            const unsigned long long* hq =
                (const unsigned long long*)&h_buf[pb * H_ + kbase];
            unsigned long long a0 = 0ull, a1 = 0ull;
            #pragma unroll
            for (int j = 0; j < 16; j++) {
                ffma2(a0, w2[2 * j],     hq[2 * j]);
                ffma2(a1, w2[2 * j + 1], hq[2 * j + 1]);
            }
            float l0, hi0, l1, hi1;
            unpack2(a0, l0, hi0);
            unpack2(a1, l1, hi1);
            part[kc * 64 + out] = (l0 + hi0) + (l1 + hi1);
            __syncthreads();                // the ONE per-step syncthreads

            if (tid < 64) {
                float s = xp + bhh;
                #pragma unroll
                for (int c = 0; c < 8; c++) s += part[c * 64 + tid];
                hn = tanhf(s);
                hh_b[(size_t)t * H_ + tid] = __float2half(hn);

                uint32_t laddr = smem_u32(&h_buf[(pb ^ 1) * H_ + grow]);
                #pragma unroll
                for (int pr = 0; pr < 8; pr++) {
                    uint32_t paddr;
                    asm("mapa.shared::cluster.u32 %0, %1, %2;"
                        : "=r"(paddr) : "r"(laddr), "r"(pr));
                    asm volatile("st.shared::cluster.f32 [%0], %1;"
                                 :: "r"(paddr), "f"(hn) : "memory");
                }
            }
            // arrive releases this thread's part-reads + DSMEM stores;
            // wait acquires peers' stores. (No second __syncthreads — every
            // thread's next part-write happens-after the cluster release.)
            asm volatile("barrier.cluster.arrive.aligned;" ::: "memory");
            asm volatile("barrier.cluster.wait.aligned;"   ::: "memory");

            if (((t & 255) == 255) && tid == 0) {
                asm volatile("red.release.gpu.global.add.u32 [%0], %1;"
                             :: "l"(&g_progress[batch][t >> 8]), "r"(1u)
                             : "memory");
            }
        }
        if (tid < 64) hfinal[batch * H_ + grow] = hn;
        __syncthreads();   // done with scan smem; fall into worker loop
    }

    // ====================== WORKER ROLE (all CTAs) ==========================
    const __half* Ah = h16;
    const uint32_t sbase = smem_u32(dsm);
    const int warp = tid >> 5, lane = tid & 31;
    const int wm = warp & 7;                 // 0..7 (M)
    const int wn = warp >> 3;                // 0..1 (N)

    const int arow = wm * 32 + (lane & 15);
    const int aoff = (lane >> 4) * 16;
    const int nrow = wn * 64 + (lane & 7) + ((lane >> 4) & 1) * 8;
    const int boff = ((lane >> 3) & 1) * 16;

    for (;;) {
        if (tid == 0) sh_tile = (int)atomicAdd(&g_ticket, 1u);
        __syncthreads();
        const int tile = sh_tile;
        if (tile >= NTILES) break;

        const int c   = tile / 1000;
        const int rem = tile - c * 1000;
        const int b   = rem / 125;
        const int nt  = rem - b * 125;
        const int mblk = b * S_ + c * 256;
        const int nblk = nt * 128;

        // wait until all 8 scan CTAs of batch b published chunk c
        if (tid == 0) {
            unsigned int v;
            for (;;) {
                asm volatile("ld.acquire.gpu.global.u32 %0, [%1];"
                             : "=r"(v) : "l"(&g_progress[b][c]) : "memory");
                if (v >= 8u) break;
                __nanosleep(256);
            }
        }
        __syncthreads();

        auto wload = [&](int kc, int st) {
            const uint32_t sst = sbase + (uint32_t)st * W_STAGE;
            #pragma unroll
            for (int j = 0; j < 6; j++) {
                int u = tid + 512 * j;
                if (u < 2048) {               // A: 256 rows x 8 chunks
                    int row = u >> 3, cc = u & 7;
                    cp_async16(sst + row * OP_PITCH + cc * 16,
                               (const char*)Ah +
                               (size_t)(mblk + row) * (H_ * 2) + kc * 128 + cc * 16);
                } else {                      // B: 128 rows x 8 chunks
                    int v2 = u - 2048;
                    int row = v2 >> 3, cc = v2 & 7;
                    cp_async16(sst + W_BOFF + row * OP_PITCH + cc * 16,
                               (const char*)Bw +
                               (size_t)(nblk + row) * (H_ * 2) + kc * 128 + cc * 16);
                }
            }
            CP_COMMIT();
        };

        float acc[2][8][4];
        #pragma unroll
        for (int mi = 0; mi < 2; mi++)
            #pragma unroll
            for (int ni = 0; ni < 8; ni++)
                #pragma unroll
                for (int q = 0; q < 4; q++) acc[mi][ni][q] = 0.f;

        wload(0, 0);
        wload(1, 1);

        #pragma unroll 1
        for (int kc = 0; kc < 8; kc++) {
            const int cur = kc & 1;
            if (kc < 7) cp_wait<1>(); else cp_wait<0>();
            __syncthreads();

            const uint32_t sst = sbase + (uint32_t)cur * W_STAGE;
            const uint32_t ahb = sst;
            const uint32_t bwb = sst + W_BOFF;

            #pragma unroll
            for (int ks = 0; ks < 4; ks++) {
                const int kb = ks * 32;
                uint32_t ah[2][4];
                #pragma unroll
                for (int mi = 0; mi < 2; mi++)
                    ldsm4(ahb + (arow + mi * 16) * OP_PITCH + kb + aoff,
                          ah[mi][0], ah[mi][1], ah[mi][2], ah[mi][3]);
                #pragma unroll
                for (int g = 0; g < 4; g++) {
                    uint32_t bh[4];
                    ldsm4(bwb + (nrow + g * 16) * OP_PITCH + kb + boff,
                          bh[0], bh[1], bh[2], bh[3]);
                    #pragma unroll
                    for (int mi = 0; mi < 2; mi++) {
                        mma_f16(acc[mi][2 * g],
                                ah[mi][0], ah[mi][1], ah[mi][2], ah[mi][3],
                                bh[0], bh[1]);
                        mma_f16(acc[mi][2 * g + 1],
                                ah[mi][0], ah[mi][1], ah[mi][2], ah[mi][3],
                                bh[2], bh[3]);
                    }
                }
            }
            __syncthreads();
            if (kc + 2 < 8) wload(kc + 2, cur);
        }

        // epilogue
        const int rg = mblk + wm * 32 + (lane >> 2);
        const int cg = nblk + wn * 64 + (lane & 3) * 2;
        #pragma unroll
        for (int mi = 0; mi < 2; mi++) {
            #pragma unroll
            for (int ni = 0; ni < 8; ni++) {
                const int row = rg + mi * 16;
                const int col = cg + ni * 8;
                const float b0 = __ldg(bias + col);
                const float b1 = __ldg(bias + col + 1);
                float2 v0 = make_float2(acc[mi][ni][0] + b0, acc[mi][ni][1] + b1);
                float2 v1 = make_float2(acc[mi][ni][2] + b0, acc[mi][ni][3] + b1);
                *(float2*)(C + (size_t)row * V_ + col)       = v0;
                *(float2*)(C + (size_t)(row + 8) * V_ + col) = v1;
            }
        }
        __syncthreads();   // tile done before smem reuse
    }
}

// ---------------------------------------------------------------------------
// Launch
// inputs: 0=x(i32)[B,S] 1=hidden[B,H] 2=embedding[V,E] 3=W_ih[H,E]
//         4=W_hh[H,H] 5=b_ih[H] 6=b_hh[H] 7=W_out[V,H] 8=b_out[V]
// output: logits [B,S,V] then h_final [B,H]
// ---------------------------------------------------------------------------
extern "C" void kernel_launch(void* const* d_in, const int* in_sizes, int n_in,
                              void* d_out, int out_size)
{
    const int*   x         = (const int*)  d_in[0];
    const float* hidden    = (const float*)d_in[1];
    const float* embedding = (const float*)d_in[2];
    const float* W_ih      = (const float*)d_in[3];
    const float* W_hh      = (const float*)d_in[4];
    const float* b_ih      = (const float*)d_in[5];
    const float* b_hh      = (const float*)d_in[6];
    const float* W_out     = (const float*)d_in[7];
    const float* b_out     = (const float*)d_in[8];
    float* out = (float*)d_out;

    float *xproj, *dummy;
    __half *h16, *w16;
    cudaGetSymbolAddress((void**)&xproj, g_xproj);
    cudaGetSymbolAddress((void**)&h16,   g_h16);
    cudaGetSymbolAddress((void**)&w16,   g_w16);
    cudaGetSymbolAddress((void**)&dummy, g_dummy_hf);

    float* hfin = ((long long)out_size >= VOUT + (long long)B_ * H_)
                      ? (out + VOUT) : dummy;

    static bool attr_done = false;
    if (!attr_done) {
        cudaFuncSetAttribute(fused_scan_logits,
                             cudaFuncAttributeMaxDynamicSharedMemorySize,
                             FUSED_SMEM);
        attr_done = true;
    }

    // 0) W_out -> fp16 ; zero overlap flags
    to_half<<<2048, 256>>>(W_out, w16, V_ * H_);
    zero_flags<<<1, 96>>>();

    // 1) x_proj = emb[x] @ W_ih^T + b_ih     [16384,512]  (fp32, full accuracy)
    gemm_nt<true><<<dim3(H_ / 128, MTOT / 128), 256>>>(
        embedding, W_ih, b_ih, xproj, x, MTOT, H_, E_);

    // 2+3) fused: scan (64 CTAs) + overlapped logits GEMM (72 workers + drain)
    fused_scan_logits<<<136, 512, FUSED_SMEM>>>(
        xproj, hidden, W_hh, b_hh, h16, hfin, w16, b_out, out);
}

// round 15
// speedup vs baseline: 1.1403x; 1.0416x over previous
#include <cuda_runtime.h>
#include <cuda_fp16.h>
#include <cstdint>

// ---------------------------------------------------------------------------
// SimpleRNN: logits = W_out( scan_tanh( W_ih·emb[x] + b_ih , W_hh, b_hh ) ) + b_out
// B=8, S=2048, E=256, H=512, V=16000
// Round 15: fused kernel, R12-exact scan role; worker CTAs split into TWO
// independent 256-thread half-engines via named barriers, each the verbatim
// measured standalone logits kernel (128x128 tile, 8 warps, 3-stage pipe).
// 16000 chunk-major 128x128 tickets; scan CTAs join the drain as halves.
// ---------------------------------------------------------------------------

#define B_  8
#define S_  2048
#define E_  256
#define H_  512
#define V_  16000
#define MTOT (B_ * S_)                      // 16384
static const long long VOUT = (long long)B_ * S_ * V_;   // 262,144,000

// Scratch (device globals: no allocation allowed)
__device__ float  g_xproj[(size_t)MTOT * H_];    // 33.5 MB
__device__ __half g_h16  [(size_t)MTOT * H_];    // 16.8 MB
__device__ __half g_w16  [(size_t)V_  * H_];     // 16.4 MB
__device__ float  g_dummy_hf[B_ * H_];
__device__ unsigned int g_progress[B_][8];       // per (batch, 256-step chunk)
__device__ unsigned int g_ticket;

// ---------------- small PTX helpers -----------------------------------------
__device__ __forceinline__ void ffma2(unsigned long long& acc,
                                      unsigned long long a,
                                      unsigned long long b) {
    asm("fma.rn.f32x2 %0, %1, %2, %0;" : "+l"(acc) : "l"(a), "l"(b));
}
__device__ __forceinline__ unsigned long long pack2(float x, float y) {
    unsigned long long r;
    asm("mov.b64 %0, {%1, %2};" : "=l"(r) : "f"(x), "f"(y));
    return r;
}
__device__ __forceinline__ void unpack2(unsigned long long v, float& lo, float& hi) {
    asm("mov.b64 {%0, %1}, %2;" : "=f"(lo), "=f"(hi) : "l"(v));
}
__device__ __forceinline__ uint32_t smem_u32(const void* p) {
    uint32_t a;
    asm("{ .reg .u64 t; cvta.to.shared.u64 t, %1; cvt.u32.u64 %0, t; }"
        : "=r"(a) : "l"(p));
    return a;
}
__device__ __forceinline__ void cp_async16(uint32_t saddr, const void* gaddr) {
    asm volatile("cp.async.cg.shared.global [%0], [%1], 16;"
                 :: "r"(saddr), "l"(gaddr));
}
#define CP_COMMIT() asm volatile("cp.async.commit_group;" ::: "memory")
template <int N>
__device__ __forceinline__ void cp_wait() {
    asm volatile("cp.async.wait_group %0;" :: "n"(N) : "memory");
}
__device__ __forceinline__ void ldsm4(uint32_t addr, uint32_t& r0, uint32_t& r1,
                                      uint32_t& r2, uint32_t& r3) {
    asm volatile("ldmatrix.sync.aligned.m8n8.x4.shared.b16 {%0,%1,%2,%3}, [%4];"
                 : "=r"(r0), "=r"(r1), "=r"(r2), "=r"(r3) : "r"(addr));
}
__device__ __forceinline__ void mma_f16(float* d,
                                        uint32_t a0, uint32_t a1,
                                        uint32_t a2, uint32_t a3,
                                        uint32_t b0, uint32_t b1) {
    asm volatile("mma.sync.aligned.m16n8k16.row.col.f32.f16.f16.f32 "
                 "{%0,%1,%2,%3}, {%4,%5,%6,%7}, {%8,%9}, {%0,%1,%2,%3};"
                 : "+f"(d[0]), "+f"(d[1]), "+f"(d[2]), "+f"(d[3])
                 : "r"(a0), "r"(a1), "r"(a2), "r"(a3), "r"(b0), "r"(b1));
}
// named barrier for one 256-thread half (ids 1,2)
__device__ __forceinline__ void barh(int half) {
    asm volatile("bar.sync %0, 256;" :: "r"(half + 1) : "memory");
}

// ---------------------------------------------------------------------------
// Kernel 0: W_out fp32 -> fp16
// ---------------------------------------------------------------------------
__global__ void to_half(const float* __restrict__ src,
                        __half* __restrict__ dst, int n)
{
    int i = blockIdx.x * blockDim.x + threadIdx.x;
    int stride = gridDim.x * blockDim.x;
    for (; i < n; i += stride) dst[i] = __float2half(src[i]);
}

// ---------------------------------------------------------------------------
// Kernel 0b: zero progress flags + ticket (re-run every graph replay)
// ---------------------------------------------------------------------------
__global__ void zero_flags()
{
    int t = threadIdx.x;
    if (t < 64) ((unsigned int*)g_progress)[t] = 0u;
    if (t == 64) g_ticket = 0u;
}

// ---------------------------------------------------------------------------
// Kernel 1: x_proj SGEMM (fp32, proven ~123us)
// ---------------------------------------------------------------------------
template <bool GATHER>
__global__ __launch_bounds__(256, 2)
void gemm_nt(const float* __restrict__ A, const float* __restrict__ Bmat,
             const float* __restrict__ bias, float* __restrict__ C,
             const int* __restrict__ idx, int M, int N, int K)
{
    __shared__ float As[2][8][128];
    __shared__ float Bs[2][8][128];

    const int tid  = threadIdx.x;
    const int mblk = blockIdx.y * 128;
    const int nblk = blockIdx.x * 128;

    const int arow = tid >> 1;
    const int kq   = (tid & 1) * 4;

    const float* Aptr;
    if (GATHER) Aptr = A + (size_t)idx[mblk + arow] * K;
    else        Aptr = A + (size_t)(mblk + arow) * K;
    const float* Bptr = Bmat + (size_t)(nblk + arow) * K;

    const int ty = tid >> 4;
    const int tx = tid & 15;

    unsigned long long acc2[8][4];
    #pragma unroll
    for (int i = 0; i < 8; i++)
        #pragma unroll
        for (int p = 0; p < 4; p++) acc2[i][p] = 0ull;

    {
        float4 a4 = *(const float4*)(Aptr + kq);
        float4 b4 = *(const float4*)(Bptr + kq);
        #pragma unroll
        for (int i = 0; i < 4; i++) {
            As[0][kq + i][arow] = ((const float*)&a4)[i];
            Bs[0][kq + i][arow] = ((const float*)&b4)[i];
        }
    }
    __syncthreads();

    const int nkt = K >> 3;
    for (int kt = 0; kt < nkt; kt++) {
        const int cur = kt & 1, nxt = cur ^ 1;
        float4 a4n, b4n;
        const bool more = (kt + 1 < nkt);
        if (more) {
            a4n = *(const float4*)(Aptr + (kt + 1) * 8 + kq);
            b4n = *(const float4*)(Bptr + (kt + 1) * 8 + kq);
        }
        #pragma unroll
        for (int k = 0; k < 8; k++) {
            float af[8];
            *(float4*)&af[0] = *(const float4*)&As[cur][k][ty * 8];
            *(float4*)&af[4] = *(const float4*)&As[cur][k][ty * 8 + 4];
            unsigned long long bp[4];
            const unsigned long long* bq =
                (const unsigned long long*)&Bs[cur][k][tx * 8];
            #pragma unroll
            for (int p = 0; p < 4; p++) bp[p] = bq[p];
            #pragma unroll
            for (int i = 0; i < 8; i++) {
                unsigned long long ad = pack2(af[i], af[i]);
                #pragma unroll
                for (int p = 0; p < 4; p++) ffma2(acc2[i][p], ad, bp[p]);
            }
        }
        if (more) {
            #pragma unroll
            for (int i = 0; i < 4; i++) {
                As[nxt][kq + i][arow] = ((const float*)&a4n)[i];
                Bs[nxt][kq + i][arow] = ((const float*)&b4n)[i];
            }
        }
        __syncthreads();
    }

    float bv[8];
    #pragma unroll
    for (int j = 0; j < 8; j++) bv[j] = bias[nblk + tx * 8 + j];

    #pragma unroll
    for (int i = 0; i < 8; i++) {
        size_t row = (size_t)(mblk + ty * 8 + i);
        float* cp = C + row * (size_t)N + nblk + tx * 8;
        float v[8];
        #pragma unroll
        for (int p = 0; p < 4; p++) {
            float lo, hi;
            unpack2(acc2[i][p], lo, hi);
            v[2 * p]     = lo + bv[2 * p];
            v[2 * p + 1] = hi + bv[2 * p + 1];
        }
        *(float4*)cp       = make_float4(v[0], v[1], v[2], v[3]);
        *(float4*)(cp + 4) = make_float4(v[4], v[5], v[6], v[7]);
    }
}

// ---------------------------------------------------------------------------
// Fused kernel: 136 CTAs x 512 thr, cluster 8 (17 clusters — all wave-1).
// Blocks 0..63  : scan (cluster = batch), EXACT R12 body (two syncs/step).
// Blocks 64..135: workers = 2 independent 256-thread half-engines (named
//                 barriers), each = measured standalone logits kernel:
//                 128x128 tile, 8 warps (4Mx2N), 3-stage cp.async.
// Tickets: 16000 chunk-major 128x128 tiles, spin on scan progress.
// ---------------------------------------------------------------------------
#define OP_PITCH   144
#define H_STG      36864              // (128+128) rows * 144B per stage
#define H_BOFF     18432              // B region offset within stage
#define HALF_SMEM  (3 * H_STG)        // 110592 per half
#define FUSED_SMEM (2 * HALF_SMEM)    // 221184
#define NTILES     16000

__global__ __launch_bounds__(512, 1) __cluster_dims__(8, 1, 1)
void fused_scan_logits(const float* __restrict__ xproj,
                       const float* __restrict__ hidden0,
                       const float* __restrict__ W_hh,
                       const float* __restrict__ b_hh,
                       __half* __restrict__ h16,
                       float* __restrict__ hfinal,
                       const __half* __restrict__ Bw,
                       const float* __restrict__ bias,
                       float* __restrict__ C)
{
    extern __shared__ char dsm[];
    __shared__ int sh_tile[2];
    const int tid = threadIdx.x;

    if (blockIdx.x < 64) {
        // =================== SCAN ROLE (R12-exact body) =====================
        float* h_buf = (float*)dsm;                  // [2][512]
        float* part  = (float*)(dsm + 4096);         // [8][64]

        const int batch = blockIdx.x >> 3;
        const int rank  = blockIdx.x & 7;
        const int out   = tid & 63;
        const int kc    = tid >> 6;
        const int kbase = kc * 64;
        const int grow  = rank * 64 + out;

        unsigned long long w2[32];
        {
            const unsigned long long* wq =
                (const unsigned long long*)(W_hh + (size_t)grow * H_ + kbase);
            #pragma unroll
            for (int j = 0; j < 32; j++) w2[j] = wq[j];
        }

        h_buf[tid] = hidden0[batch * H_ + tid];
        const float bhh = (tid < 64) ? b_hh[rank * 64 + tid] : 0.f;
        __syncthreads();
        asm volatile("barrier.cluster.arrive.aligned;" ::: "memory");
        asm volatile("barrier.cluster.wait.aligned;"   ::: "memory");

        const float* xp_b = xproj + (size_t)batch * S_ * H_ + rank * 64;
        __half*      hh_b = h16   + (size_t)batch * S_ * H_ + rank * 64;

        float hn = 0.f;
        for (int t = 0; t < S_; t++) {
            const int pb = t & 1;

            float xp = 0.f;
            if (tid < 64) xp = xp_b[(size_t)t * H_ + tid];

            const unsigned long long* hq =
                (const unsigned long long*)&h_buf[pb * H_ + kbase];
            unsigned long long a0 = 0ull, a1 = 0ull;
            #pragma unroll
            for (int j = 0; j < 16; j++) {
                ffma2(a0, w2[2 * j],     hq[2 * j]);
                ffma2(a1, w2[2 * j + 1], hq[2 * j + 1]);
            }
            float l0, hi0, l1, hi1;
            unpack2(a0, l0, hi0);
            unpack2(a1, l1, hi1);
            part[kc * 64 + out] = (l0 + hi0) + (l1 + hi1);
            __syncthreads();

            if (tid < 64) {
                float s = xp + bhh;
                #pragma unroll
                for (int c = 0; c < 8; c++) s += part[c * 64 + tid];
                hn = tanhf(s);
                hh_b[(size_t)t * H_ + tid] = __float2half(hn);

                uint32_t laddr = smem_u32(&h_buf[(pb ^ 1) * H_ + grow]);
                #pragma unroll
                for (int pr = 0; pr < 8; pr++) {
                    uint32_t paddr;
                    asm("mapa.shared::cluster.u32 %0, %1, %2;"
                        : "=r"(paddr) : "r"(laddr), "r"(pr));
                    asm volatile("st.shared::cluster.f32 [%0], %1;"
                                 :: "r"(paddr), "f"(hn) : "memory");
                }
            }
            __syncthreads();
            asm volatile("barrier.cluster.arrive.aligned;" ::: "memory");
            asm volatile("barrier.cluster.wait.aligned;"   ::: "memory");

            if (((t & 255) == 255) && tid == 0) {
                asm volatile("red.release.gpu.global.add.u32 [%0], %1;"
                             :: "l"(&g_progress[batch][t >> 8]), "r"(1u)
                             : "memory");
            }
        }
        if (tid < 64) hfinal[batch * H_ + grow] = hn;
        __syncthreads();   // done with scan smem; fall into worker role
    }

    // ============ WORKER ROLE: two independent 256-thread halves ============
    const __half* Ah = h16;
    const int half = tid >> 8;               // 0 or 1
    const int htid = tid & 255;
    const uint32_t hbase = smem_u32(dsm) + (uint32_t)half * HALF_SMEM;

    const int warp = htid >> 5, lane = htid & 31;
    const int wm = warp & 3;                 // 0..3 (M)
    const int wn = warp >> 2;                // 0..1 (N)

    const int arow = wm * 32 + (lane & 15);
    const int aoff = (lane >> 4) * 16;
    const int nrow = wn * 64 + (lane & 7) + ((lane >> 4) & 1) * 8;
    const int boff = ((lane >> 3) & 1) * 16;

    for (;;) {
        if (htid == 0) sh_tile[half] = (int)atomicAdd(&g_ticket, 1u);
        barh(half);
        const int tile = sh_tile[half];
        barh(half);                            // sh_tile stable before reuse
        if (tile >= NTILES) break;

        // chunk-major 128x128 tile map
        const int c   = tile / 2000;
        const int rem = tile - c * 2000;
        const int b   = rem / 250;
        const int r2  = rem - b * 250;
        const int m2  = r2 / 125;
        const int nt  = r2 - m2 * 125;
        const int mblk = b * S_ + c * 256 + m2 * 128;
        const int nblk = nt * 128;

        if (htid == 0) {
            unsigned int v;
            for (;;) {
                asm volatile("ld.acquire.gpu.global.u32 %0, [%1];"
                             : "=r"(v) : "l"(&g_progress[b][c]) : "memory");
                if (v >= 8u) break;
                __nanosleep(256);
            }
        }
        barh(half);

        auto load_stage = [&](int kc, int st) {
            const uint32_t sst = hbase + (uint32_t)st * H_STG;
            #pragma unroll
            for (int j = 0; j < 4; j++) {
                int u = htid + 256 * j;
                int row = u >> 3, cc = u & 7;
                cp_async16(sst + row * OP_PITCH + cc * 16,
                           (const char*)Ah +
                           (size_t)(mblk + row) * (H_ * 2) + kc * 128 + cc * 16);
            }
            #pragma unroll
            for (int j = 0; j < 4; j++) {
                int u = htid + 256 * j;
                int row = u >> 3, cc = u & 7;
                cp_async16(sst + H_BOFF + row * OP_PITCH + cc * 16,
                           (const char*)Bw +
                           (size_t)(nblk + row) * (H_ * 2) + kc * 128 + cc * 16);
            }
            CP_COMMIT();
        };

        float acc[2][8][4];
        #pragma unroll
        for (int mi = 0; mi < 2; mi++)
            #pragma unroll
            for (int ni = 0; ni < 8; ni++)
                #pragma unroll
                for (int q = 0; q < 4; q++) acc[mi][ni][q] = 0.f;

        load_stage(0, 0);
        load_stage(1, 1);

        #pragma unroll 1
        for (int kc = 0; kc < 8; kc++) {
            const int st = kc - (kc / 3) * 3;     // kc % 3
            cp_wait<1>();
            barh(half);

            if (kc + 2 < 8) load_stage(kc + 2, (kc + 2) % 3);
            else            CP_COMMIT();          // keep group accounting

            const uint32_t sst = hbase + (uint32_t)st * H_STG;
            const uint32_t ahb = sst;
            const uint32_t bwb = sst + H_BOFF;

            #pragma unroll
            for (int ks = 0; ks < 4; ks++) {
                const int kb = ks * 32;
                uint32_t ah[2][4];
                #pragma unroll
                for (int mi = 0; mi < 2; mi++)
                    ldsm4(ahb + (arow + mi * 16) * OP_PITCH + kb + aoff,
                          ah[mi][0], ah[mi][1], ah[mi][2], ah[mi][3]);
                #pragma unroll
                for (int g = 0; g < 4; g++) {
                    uint32_t bh[4];
                    ldsm4(bwb + (nrow + g * 16) * OP_PITCH + kb + boff,
                          bh[0], bh[1], bh[2], bh[3]);
                    #pragma unroll
                    for (int mi = 0; mi < 2; mi++) {
                        mma_f16(acc[mi][2 * g],
                                ah[mi][0], ah[mi][1], ah[mi][2], ah[mi][3],
                                bh[0], bh[1]);
                        mma_f16(acc[mi][2 * g + 1],
                                ah[mi][0], ah[mi][1], ah[mi][2], ah[mi][3],
                                bh[2], bh[3]);
                    }
                }
            }
        }

        // epilogue
        const int rg = mblk + wm * 32 + (lane >> 2);
        const int cg = nblk + wn * 64 + (lane & 3) * 2;
        #pragma unroll
        for (int mi = 0; mi < 2; mi++) {
            #pragma unroll
            for (int ni = 0; ni < 8; ni++) {
                const int row = rg + mi * 16;
                const int col = cg + ni * 8;
                const float b0 = __ldg(bias + col);
                const float b1 = __ldg(bias + col + 1);
                float2 v0 = make_float2(acc[mi][ni][0] + b0, acc[mi][ni][1] + b1);
                float2 v1 = make_float2(acc[mi][ni][2] + b0, acc[mi][ni][3] + b1);
                *(float2*)(C + (size_t)row * V_ + col)       = v0;
                *(float2*)(C + (size_t)(row + 8) * V_ + col) = v1;
            }
        }
        barh(half);    // epilogue reads done before smem/sh_tile reuse
    }
}

// ---------------------------------------------------------------------------
// Launch
// inputs: 0=x(i32)[B,S] 1=hidden[B,H] 2=embedding[V,E] 3=W_ih[H,E]
//         4=W_hh[H,H] 5=b_ih[H] 6=b_hh[H] 7=W_out[V,H] 8=b_out[V]
// output: logits [B,S,V] then h_final [B,H]
// ---------------------------------------------------------------------------
extern "C" void kernel_launch(void* const* d_in, const int* in_sizes, int n_in,
                              void* d_out, int out_size)
{
    const int*   x         = (const int*)  d_in[0];
    const float* hidden    = (const float*)d_in[1];
    const float* embedding = (const float*)d_in[2];
    const float* W_ih      = (const float*)d_in[3];
    const float* W_hh      = (const float*)d_in[4];
    const float* b_ih      = (const float*)d_in[5];
    const float* b_hh      = (const float*)d_in[6];
    const float* W_out     = (const float*)d_in[7];
    const float* b_out     = (const float*)d_in[8];
    float* out = (float*)d_out;

    float *xproj, *dummy;
    __half *h16, *w16;
    cudaGetSymbolAddress((void**)&xproj, g_xproj);
    cudaGetSymbolAddress((void**)&h16,   g_h16);
    cudaGetSymbolAddress((void**)&w16,   g_w16);
    cudaGetSymbolAddress((void**)&dummy, g_dummy_hf);

    float* hfin = ((long long)out_size >= VOUT + (long long)B_ * H_)
                      ? (out + VOUT) : dummy;

    static bool attr_done = false;
    if (!attr_done) {
        cudaFuncSetAttribute(fused_scan_logits,
                             cudaFuncAttributeMaxDynamicSharedMemorySize,
                             FUSED_SMEM);
        attr_done = true;
    }

    // 0) W_out -> fp16 ; zero overlap flags
    to_half<<<2048, 256>>>(W_out, w16, V_ * H_);
    zero_flags<<<1, 96>>>();

    // 1) x_proj = emb[x] @ W_ih^T + b_ih     [16384,512]  (fp32, full accuracy)
    gemm_nt<true><<<dim3(H_ / 128, MTOT / 128), 256>>>(
        embedding, W_ih, b_ih, xproj, x, MTOT, H_, E_);

    // 2+3) fused: scan (64 CTAs) + overlapped logits GEMM (72x2 half-engines
    //      + full-chip drain)
    fused_scan_logits<<<136, 512, FUSED_SMEM>>>(
        xproj, hidden, W_hh, b_hh, h16, hfin, w16, b_out, out);
}

// round 16
// speedup vs baseline: 1.1535x; 1.0116x over previous
#include <cuda_runtime.h>
#include <cuda_fp16.h>
#include <cstdint>

// ---------------------------------------------------------------------------
// SimpleRNN: logits = W_out( scan_tanh( W_ih·emb[x] + b_ih , W_hh, b_hh ) ) + b_out
// B=8, S=2048, E=256, H=512, V=16000
// Round 16: R15 winner with ONE change — scan progress published every 128
// steps (was 256) and logits tiles re-keyed to 128-row chunks, halving the
// end-of-scan backlog that lands on the critical path.
// ---------------------------------------------------------------------------

#define B_  8
#define S_  2048
#define E_  256
#define H_  512
#define V_  16000
#define MTOT (B_ * S_)                      // 16384
static const long long VOUT = (long long)B_ * S_ * V_;   // 262,144,000

// Scratch (device globals: no allocation allowed)
__device__ float  g_xproj[(size_t)MTOT * H_];    // 33.5 MB
__device__ __half g_h16  [(size_t)MTOT * H_];    // 16.8 MB
__device__ __half g_w16  [(size_t)V_  * H_];     // 16.4 MB
__device__ float  g_dummy_hf[B_ * H_];
__device__ unsigned int g_progress[B_][16];      // per (batch, 128-step chunk)
__device__ unsigned int g_ticket;

// ---------------- small PTX helpers -----------------------------------------
__device__ __forceinline__ void ffma2(unsigned long long& acc,
                                      unsigned long long a,
                                      unsigned long long b) {
    asm("fma.rn.f32x2 %0, %1, %2, %0;" : "+l"(acc) : "l"(a), "l"(b));
}
__device__ __forceinline__ unsigned long long pack2(float x, float y) {
    unsigned long long r;
    asm("mov.b64 %0, {%1, %2};" : "=l"(r) : "f"(x), "f"(y));
    return r;
}
__device__ __forceinline__ void unpack2(unsigned long long v, float& lo, float& hi) {
    asm("mov.b64 {%0, %1}, %2;" : "=f"(lo), "=f"(hi) : "l"(v));
}
__device__ __forceinline__ uint32_t smem_u32(const void* p) {
    uint32_t a;
    asm("{ .reg .u64 t; cvta.to.shared.u64 t, %1; cvt.u32.u64 %0, t; }"
        : "=r"(a) : "l"(p));
    return a;
}
__device__ __forceinline__ void cp_async16(uint32_t saddr, const void* gaddr) {
    asm volatile("cp.async.cg.shared.global [%0], [%1], 16;"
                 :: "r"(saddr), "l"(gaddr));
}
#define CP_COMMIT() asm volatile("cp.async.commit_group;" ::: "memory")
template <int N>
__device__ __forceinline__ void cp_wait() {
    asm volatile("cp.async.wait_group %0;" :: "n"(N) : "memory");
}
__device__ __forceinline__ void ldsm4(uint32_t addr, uint32_t& r0, uint32_t& r1,
                                      uint32_t& r2, uint32_t& r3) {
    asm volatile("ldmatrix.sync.aligned.m8n8.x4.shared.b16 {%0,%1,%2,%3}, [%4];"
                 : "=r"(r0), "=r"(r1), "=r"(r2), "=r"(r3) : "r"(addr));
}
__device__ __forceinline__ void mma_f16(float* d,
                                        uint32_t a0, uint32_t a1,
                                        uint32_t a2, uint32_t a3,
                                        uint32_t b0, uint32_t b1) {
    asm volatile("mma.sync.aligned.m16n8k16.row.col.f32.f16.f16.f32 "
                 "{%0,%1,%2,%3}, {%4,%5,%6,%7}, {%8,%9}, {%0,%1,%2,%3};"
                 : "+f"(d[0]), "+f"(d[1]), "+f"(d[2]), "+f"(d[3])
                 : "r"(a0), "r"(a1), "r"(a2), "r"(a3), "r"(b0), "r"(b1));
}
// named barrier for one 256-thread half (ids 1,2)
__device__ __forceinline__ void barh(int half) {
    asm volatile("bar.sync %0, 256;" :: "r"(half + 1) : "memory");
}

// ---------------------------------------------------------------------------
// Kernel 0: W_out fp32 -> fp16
// ---------------------------------------------------------------------------
__global__ void to_half(const float* __restrict__ src,
                        __half* __restrict__ dst, int n)
{
    int i = blockIdx.x * blockDim.x + threadIdx.x;
    int stride = gridDim.x * blockDim.x;
    for (; i < n; i += stride) dst[i] = __float2half(src[i]);
}

// ---------------------------------------------------------------------------
// Kernel 0b: zero progress flags + ticket (re-run every graph replay)
// ---------------------------------------------------------------------------
__global__ void zero_flags()
{
    int t = threadIdx.x;
    if (t < 128) ((unsigned int*)g_progress)[t] = 0u;
    if (t == 128) g_ticket = 0u;
}

// ---------------------------------------------------------------------------
// Kernel 1: x_proj SGEMM (fp32, proven ~123us)
// ---------------------------------------------------------------------------
template <bool GATHER>
__global__ __launch_bounds__(256, 2)
void gemm_nt(const float* __restrict__ A, const float* __restrict__ Bmat,
             const float* __restrict__ bias, float* __restrict__ C,
             const int* __restrict__ idx, int M, int N, int K)
{
    __shared__ float As[2][8][128];
    __shared__ float Bs[2][8][128];

    const int tid  = threadIdx.x;
    const int mblk = blockIdx.y * 128;
    const int nblk = blockIdx.x * 128;

    const int arow = tid >> 1;
    const int kq   = (tid & 1) * 4;

    const float* Aptr;
    if (GATHER) Aptr = A + (size_t)idx[mblk + arow] * K;
    else        Aptr = A + (size_t)(mblk + arow) * K;
    const float* Bptr = Bmat + (size_t)(nblk + arow) * K;

    const int ty = tid >> 4;
    const int tx = tid & 15;

    unsigned long long acc2[8][4];
    #pragma unroll
    for (int i = 0; i < 8; i++)
        #pragma unroll
        for (int p = 0; p < 4; p++) acc2[i][p] = 0ull;

    {
        float4 a4 = *(const float4*)(Aptr + kq);
        float4 b4 = *(const float4*)(Bptr + kq);
        #pragma unroll
        for (int i = 0; i < 4; i++) {
            As[0][kq + i][arow] = ((const float*)&a4)[i];
            Bs[0][kq + i][arow] = ((const float*)&b4)[i];
        }
    }
    __syncthreads();

    const int nkt = K >> 3;
    for (int kt = 0; kt < nkt; kt++) {
        const int cur = kt & 1, nxt = cur ^ 1;
        float4 a4n, b4n;
        const bool more = (kt + 1 < nkt);
        if (more) {
            a4n = *(const float4*)(Aptr + (kt + 1) * 8 + kq);
            b4n = *(const float4*)(Bptr + (kt + 1) * 8 + kq);
        }
        #pragma unroll
        for (int k = 0; k < 8; k++) {
            float af[8];
            *(float4*)&af[0] = *(const float4*)&As[cur][k][ty * 8];
            *(float4*)&af[4] = *(const float4*)&As[cur][k][ty * 8 + 4];
            unsigned long long bp[4];
            const unsigned long long* bq =
                (const unsigned long long*)&Bs[cur][k][tx * 8];
            #pragma unroll
            for (int p = 0; p < 4; p++) bp[p] = bq[p];
            #pragma unroll
            for (int i = 0; i < 8; i++) {
                unsigned long long ad = pack2(af[i], af[i]);
                #pragma unroll
                for (int p = 0; p < 4; p++) ffma2(acc2[i][p], ad, bp[p]);
            }
        }
        if (more) {
            #pragma unroll
            for (int i = 0; i < 4; i++) {
                As[nxt][kq + i][arow] = ((const float*)&a4n)[i];
                Bs[nxt][kq + i][arow] = ((const float*)&b4n)[i];
            }
        }
        __syncthreads();
    }

    float bv[8];
    #pragma unroll
    for (int j = 0; j < 8; j++) bv[j] = bias[nblk + tx * 8 + j];

    #pragma unroll
    for (int i = 0; i < 8; i++) {
        size_t row = (size_t)(mblk + ty * 8 + i);
        float* cp = C + row * (size_t)N + nblk + tx * 8;
        float v[8];
        #pragma unroll
        for (int p = 0; p < 4; p++) {
            float lo, hi;
            unpack2(acc2[i][p], lo, hi);
            v[2 * p]     = lo + bv[2 * p];
            v[2 * p + 1] = hi + bv[2 * p + 1];
        }
        *(float4*)cp       = make_float4(v[0], v[1], v[2], v[3]);
        *(float4*)(cp + 4) = make_float4(v[4], v[5], v[6], v[7]);
    }
}

// ---------------------------------------------------------------------------
// Fused kernel: 136 CTAs x 512 thr, cluster 8 (17 clusters — all wave-1).
// Blocks 0..63  : scan (cluster = batch), EXACT R12 body; progress published
//                 every 128 steps (16 chunks).
// Blocks 64..135: workers = 2 independent 256-thread half-engines (named
//                 barriers), each = measured standalone logits kernel:
//                 128x128 tile, 8 warps (4Mx2N), 3-stage cp.async.
// Tickets: 16000 = 16 chunks x 8 batches x 125 n-tiles (chunk-major).
// ---------------------------------------------------------------------------
#define OP_PITCH   144
#define H_STG      36864              // (128+128) rows * 144B per stage
#define H_BOFF     18432              // B region offset within stage
#define HALF_SMEM  (3 * H_STG)        // 110592 per half
#define FUSED_SMEM (2 * HALF_SMEM)    // 221184
#define NTILES     16000

__global__ __launch_bounds__(512, 1) __cluster_dims__(8, 1, 1)
void fused_scan_logits(const float* __restrict__ xproj,
                       const float* __restrict__ hidden0,
                       const float* __restrict__ W_hh,
                       const float* __restrict__ b_hh,
                       __half* __restrict__ h16,
                       float* __restrict__ hfinal,
                       const __half* __restrict__ Bw,
                       const float* __restrict__ bias,
                       float* __restrict__ C)
{
    extern __shared__ char dsm[];
    __shared__ int sh_tile[2];
    const int tid = threadIdx.x;

    if (blockIdx.x < 64) {
        // =================== SCAN ROLE (R12-exact body) =====================
        float* h_buf = (float*)dsm;                  // [2][512]
        float* part  = (float*)(dsm + 4096);         // [8][64]

        const int batch = blockIdx.x >> 3;
        const int rank  = blockIdx.x & 7;
        const int out   = tid & 63;
        const int kc    = tid >> 6;
        const int kbase = kc * 64;
        const int grow  = rank * 64 + out;

        unsigned long long w2[32];
        {
            const unsigned long long* wq =
                (const unsigned long long*)(W_hh + (size_t)grow * H_ + kbase);
            #pragma unroll
            for (int j = 0; j < 32; j++) w2[j] = wq[j];
        }

        h_buf[tid] = hidden0[batch * H_ + tid];
        const float bhh = (tid < 64) ? b_hh[rank * 64 + tid] : 0.f;
        __syncthreads();
        asm volatile("barrier.cluster.arrive.aligned;" ::: "memory");
        asm volatile("barrier.cluster.wait.aligned;"   ::: "memory");

        const float* xp_b = xproj + (size_t)batch * S_ * H_ + rank * 64;
        __half*      hh_b = h16   + (size_t)batch * S_ * H_ + rank * 64;

        float hn = 0.f;
        for (int t = 0; t < S_; t++) {
            const int pb = t & 1;

            float xp = 0.f;
            if (tid < 64) xp = xp_b[(size_t)t * H_ + tid];

            const unsigned long long* hq =
                (const unsigned long long*)&h_buf[pb * H_ + kbase];
            unsigned long long a0 = 0ull, a1 = 0ull;
            #pragma unroll
            for (int j = 0; j < 16; j++) {
                ffma2(a0, w2[2 * j],     hq[2 * j]);
                ffma2(a1, w2[2 * j + 1], hq[2 * j + 1]);
            }
            float l0, hi0, l1, hi1;
            unpack2(a0, l0, hi0);
            unpack2(a1, l1, hi1);
            part[kc * 64 + out] = (l0 + hi0) + (l1 + hi1);
            __syncthreads();

            if (tid < 64) {
                float s = xp + bhh;
                #pragma unroll
                for (int c = 0; c < 8; c++) s += part[c * 64 + tid];
                hn = tanhf(s);
                hh_b[(size_t)t * H_ + tid] = __float2half(hn);

                uint32_t laddr = smem_u32(&h_buf[(pb ^ 1) * H_ + grow]);
                #pragma unroll
                for (int pr = 0; pr < 8; pr++) {
                    uint32_t paddr;
                    asm("mapa.shared::cluster.u32 %0, %1, %2;"
                        : "=r"(paddr) : "r"(laddr), "r"(pr));
                    asm volatile("st.shared::cluster.f32 [%0], %1;"
                                 :: "r"(paddr), "f"(hn) : "memory");
                }
            }
            __syncthreads();
            asm volatile("barrier.cluster.arrive.aligned;" ::: "memory");
            asm volatile("barrier.cluster.wait.aligned;"   ::: "memory");

            // publish completed 128-step chunk
            if (((t & 127) == 127) && tid == 0) {
                asm volatile("red.release.gpu.global.add.u32 [%0], %1;"
                             :: "l"(&g_progress[batch][t >> 7]), "r"(1u)
                             : "memory");
            }
        }
        if (tid < 64) hfinal[batch * H_ + grow] = hn;
        __syncthreads();   // done with scan smem; fall into worker role
    }

    // ============ WORKER ROLE: two independent 256-thread halves ============
    const __half* Ah = h16;
    const int half = tid >> 8;               // 0 or 1
    const int htid = tid & 255;
    const uint32_t hbase = smem_u32(dsm) + (uint32_t)half * HALF_SMEM;

    const int warp = htid >> 5, lane = htid & 31;
    const int wm = warp & 3;                 // 0..3 (M)
    const int wn = warp >> 2;                // 0..1 (N)

    const int arow = wm * 32 + (lane & 15);
    const int aoff = (lane >> 4) * 16;
    const int nrow = wn * 64 + (lane & 7) + ((lane >> 4) & 1) * 8;
    const int boff = ((lane >> 3) & 1) * 16;

    for (;;) {
        if (htid == 0) sh_tile[half] = (int)atomicAdd(&g_ticket, 1u);
        barh(half);
        const int tile = sh_tile[half];
        barh(half);                            // sh_tile stable before reuse
        if (tile >= NTILES) break;

        // chunk-major 128x128 tile map over 16 chunks of 128 rows
        const int c   = tile / 1000;          // 0..15
        const int rem = tile - c * 1000;
        const int b   = rem / 125;
        const int nt  = rem - b * 125;
        const int mblk = b * S_ + c * 128;
        const int nblk = nt * 128;

        if (htid == 0) {
            unsigned int v;
            for (;;) {
                asm volatile("ld.acquire.gpu.global.u32 %0, [%1];"
                             : "=r"(v) : "l"(&g_progress[b][c]) : "memory");
                if (v >= 8u) break;
                __nanosleep(256);
            }
        }
        barh(half);

        auto load_stage = [&](int kc, int st) {
            const uint32_t sst = hbase + (uint32_t)st * H_STG;
            #pragma unroll
            for (int j = 0; j < 4; j++) {
                int u = htid + 256 * j;
                int row = u >> 3, cc = u & 7;
                cp_async16(sst + row * OP_PITCH + cc * 16,
                           (const char*)Ah +
                           (size_t)(mblk + row) * (H_ * 2) + kc * 128 + cc * 16);
            }
            #pragma unroll
            for (int j = 0; j < 4; j++) {
                int u = htid + 256 * j;
                int row = u >> 3, cc = u & 7;
                cp_async16(sst + H_BOFF + row * OP_PITCH + cc * 16,
                           (const char*)Bw +
                           (size_t)(nblk + row) * (H_ * 2) + kc * 128 + cc * 16);
            }
            CP_COMMIT();
        };

        float acc[2][8][4];
        #pragma unroll
        for (int mi = 0; mi < 2; mi++)
            #pragma unroll
            for (int ni = 0; ni < 8; ni++)
                #pragma unroll
                for (int q = 0; q < 4; q++) acc[mi][ni][q] = 0.f;

        load_stage(0, 0);
        load_stage(1, 1);

        #pragma unroll 1
        for (int kc = 0; kc < 8; kc++) {
            const int st = kc - (kc / 3) * 3;     // kc % 3
            cp_wait<1>();
            barh(half);

            if (kc + 2 < 8) load_stage(kc + 2, (kc + 2) % 3);
            else            CP_COMMIT();          // keep group accounting

            const uint32_t sst = hbase + (uint32_t)st * H_STG;
            const uint32_t ahb = sst;
            const uint32_t bwb = sst + H_BOFF;

            #pragma unroll
            for (int ks = 0; ks < 4; ks++) {
                const int kb = ks * 32;
                uint32_t ah[2][4];
                #pragma unroll
                for (int mi = 0; mi < 2; mi++)
                    ldsm4(ahb + (arow + mi * 16) * OP_PITCH + kb + aoff,
                          ah[mi][0], ah[mi][1], ah[mi][2], ah[mi][3]);
                #pragma unroll
                for (int g = 0; g < 4; g++) {
                    uint32_t bh[4];
                    ldsm4(bwb + (nrow + g * 16) * OP_PITCH + kb + boff,
                          bh[0], bh[1], bh[2], bh[3]);
                    #pragma unroll
                    for (int mi = 0; mi < 2; mi++) {
                        mma_f16(acc[mi][2 * g],
                                ah[mi][0], ah[mi][1], ah[mi][2], ah[mi][3],
                                bh[0], bh[1]);
                        mma_f16(acc[mi][2 * g + 1],
                                ah[mi][0], ah[mi][1], ah[mi][2], ah[mi][3],
                                bh[2], bh[3]);
                    }
                }
            }
        }

        // epilogue
        const int rg = mblk + wm * 32 + (lane >> 2);
        const int cg = nblk + wn * 64 + (lane & 3) * 2;
        #pragma unroll
        for (int mi = 0; mi < 2; mi++) {
            #pragma unroll
            for (int ni = 0; ni < 8; ni++) {
                const int row = rg + mi * 16;
                const int col = cg + ni * 8;
                const float b0 = __ldg(bias + col);
                const float b1 = __ldg(bias + col + 1);
                float2 v0 = make_float2(acc[mi][ni][0] + b0, acc[mi][ni][1] + b1);
                float2 v1 = make_float2(acc[mi][ni][2] + b0, acc[mi][ni][3] + b1);
                *(float2*)(C + (size_t)row * V_ + col)       = v0;
                *(float2*)(C + (size_t)(row + 8) * V_ + col) = v1;
            }
        }
        barh(half);    // epilogue reads done before smem/sh_tile reuse
    }
}

// ---------------------------------------------------------------------------
// Launch
// inputs: 0=x(i32)[B,S] 1=hidden[B,H] 2=embedding[V,E] 3=W_ih[H,E]
//         4=W_hh[H,H] 5=b_ih[H] 6=b_hh[H] 7=W_out[V,H] 8=b_out[V]
// output: logits [B,S,V] then h_final [B,H]
// ---------------------------------------------------------------------------
extern "C" void kernel_launch(void* const* d_in, const int* in_sizes, int n_in,
                              void* d_out, int out_size)
{
    const int*   x         = (const int*)  d_in[0];
    const float* hidden    = (const float*)d_in[1];
    const float* embedding = (const float*)d_in[2];
    const float* W_ih      = (const float*)d_in[3];
    const float* W_hh      = (const float*)d_in[4];
    const float* b_ih      = (const float*)d_in[5];
    const float* b_hh      = (const float*)d_in[6];
    const float* W_out     = (const float*)d_in[7];
    const float* b_out     = (const float*)d_in[8];
    float* out = (float*)d_out;

    float *xproj, *dummy;
    __half *h16, *w16;
    cudaGetSymbolAddress((void**)&xproj, g_xproj);
    cudaGetSymbolAddress((void**)&h16,   g_h16);
    cudaGetSymbolAddress((void**)&w16,   g_w16);
    cudaGetSymbolAddress((void**)&dummy, g_dummy_hf);

    float* hfin = ((long long)out_size >= VOUT + (long long)B_ * H_)
                      ? (out + VOUT) : dummy;

    static bool attr_done = false;
    if (!attr_done) {
        cudaFuncSetAttribute(fused_scan_logits,
                             cudaFuncAttributeMaxDynamicSharedMemorySize,
                             FUSED_SMEM);
        attr_done = true;
    }

    // 0) W_out -> fp16 ; zero overlap flags
    to_half<<<2048, 256>>>(W_out, w16, V_ * H_);
    zero_flags<<<1, 160>>>();

    // 1) x_proj = emb[x] @ W_ih^T + b_ih     [16384,512]  (fp32, full accuracy)
    gemm_nt<true><<<dim3(H_ / 128, MTOT / 128), 256>>>(
        embedding, W_ih, b_ih, xproj, x, MTOT, H_, E_);

    // 2+3) fused: scan (64 CTAs) + overlapped logits GEMM (72x2 half-engines
    //      + full-chip drain)
    fused_scan_logits<<<136, 512, FUSED_SMEM>>>(
        xproj, hidden, W_hh, b_hh, h16, hfin, w16, b_out, out);
}

// round 17
// speedup vs baseline: 1.2585x; 1.0910x over previous
#include <cuda_runtime.h>
#include <cuda_fp16.h>
#include <cstdint>

// ---------------------------------------------------------------------------
// SimpleRNN: logits = W_out( scan_tanh( W_ih·emb[x] + b_ih , W_hh, b_hh ) ) + b_out
// B=8, S=2048, E=256, H=512, V=16000
// Round 17: R16 winner with ONE change — scan stages each 128-step xproj
// chunk into SMEM via cp.async double-buffer (32KB/chunk), turning the
// per-step global xp read (L2-latency-exposed under worker load) into a
// 29-cyc conflict-free LDS.
// ---------------------------------------------------------------------------

#define B_  8
#define S_  2048
#define E_  256
#define H_  512
#define V_  16000
#define MTOT (B_ * S_)                      // 16384
static const long long VOUT = (long long)B_ * S_ * V_;   // 262,144,000

// Scratch (device globals: no allocation allowed)
__device__ float  g_xproj[(size_t)MTOT * H_];    // 33.5 MB
__device__ __half g_h16  [(size_t)MTOT * H_];    // 16.8 MB
__device__ __half g_w16  [(size_t)V_  * H_];     // 16.4 MB
__device__ float  g_dummy_hf[B_ * H_];
__device__ unsigned int g_progress[B_][16];      // per (batch, 128-step chunk)
__device__ unsigned int g_ticket;

// ---------------- small PTX helpers -----------------------------------------
__device__ __forceinline__ void ffma2(unsigned long long& acc,
                                      unsigned long long a,
                                      unsigned long long b) {
    asm("fma.rn.f32x2 %0, %1, %2, %0;" : "+l"(acc) : "l"(a), "l"(b));
}
__device__ __forceinline__ unsigned long long pack2(float x, float y) {
    unsigned long long r;
    asm("mov.b64 %0, {%1, %2};" : "=l"(r) : "f"(x), "f"(y));
    return r;
}
__device__ __forceinline__ void unpack2(unsigned long long v, float& lo, float& hi) {
    asm("mov.b64 {%0, %1}, %2;" : "=f"(lo), "=f"(hi) : "l"(v));
}
__device__ __forceinline__ uint32_t smem_u32(const void* p) {
    uint32_t a;
    asm("{ .reg .u64 t; cvta.to.shared.u64 t, %1; cvt.u32.u64 %0, t; }"
        : "=r"(a) : "l"(p));
    return a;
}
__device__ __forceinline__ void cp_async16(uint32_t saddr, const void* gaddr) {
    asm volatile("cp.async.cg.shared.global [%0], [%1], 16;"
                 :: "r"(saddr), "l"(gaddr));
}
#define CP_COMMIT() asm volatile("cp.async.commit_group;" ::: "memory")
template <int N>
__device__ __forceinline__ void cp_wait() {
    asm volatile("cp.async.wait_group %0;" :: "n"(N) : "memory");
}
__device__ __forceinline__ void ldsm4(uint32_t addr, uint32_t& r0, uint32_t& r1,
                                      uint32_t& r2, uint32_t& r3) {
    asm volatile("ldmatrix.sync.aligned.m8n8.x4.shared.b16 {%0,%1,%2,%3}, [%4];"
                 : "=r"(r0), "=r"(r1), "=r"(r2), "=r"(r3) : "r"(addr));
}
__device__ __forceinline__ void mma_f16(float* d,
                                        uint32_t a0, uint32_t a1,
                                        uint32_t a2, uint32_t a3,
                                        uint32_t b0, uint32_t b1) {
    asm volatile("mma.sync.aligned.m16n8k16.row.col.f32.f16.f16.f32 "
                 "{%0,%1,%2,%3}, {%4,%5,%6,%7}, {%8,%9}, {%0,%1,%2,%3};"
                 : "+f"(d[0]), "+f"(d[1]), "+f"(d[2]), "+f"(d[3])
                 : "r"(a0), "r"(a1), "r"(a2), "r"(a3), "r"(b0), "r"(b1));
}
// named barrier for one 256-thread half (ids 1,2)
__device__ __forceinline__ void barh(int half) {
    asm volatile("bar.sync %0, 256;" :: "r"(half + 1) : "memory");
}

// ---------------------------------------------------------------------------
// Kernel 0: W_out fp32 -> fp16
// ---------------------------------------------------------------------------
__global__ void to_half(const float* __restrict__ src,
                        __half* __restrict__ dst, int n)
{
    int i = blockIdx.x * blockDim.x + threadIdx.x;
    int stride = gridDim.x * blockDim.x;
    for (; i < n; i += stride) dst[i] = __float2half(src[i]);
}

// ---------------------------------------------------------------------------
// Kernel 0b: zero progress flags + ticket (re-run every graph replay)
// ---------------------------------------------------------------------------
__global__ void zero_flags()
{
    int t = threadIdx.x;
    if (t < 128) ((unsigned int*)g_progress)[t] = 0u;
    if (t == 128) g_ticket = 0u;
}

// ---------------------------------------------------------------------------
// Kernel 1: x_proj SGEMM (fp32, proven ~123us)
// ---------------------------------------------------------------------------
template <bool GATHER>
__global__ __launch_bounds__(256, 2)
void gemm_nt(const float* __restrict__ A, const float* __restrict__ Bmat,
             const float* __restrict__ bias, float* __restrict__ C,
             const int* __restrict__ idx, int M, int N, int K)
{
    __shared__ float As[2][8][128];
    __shared__ float Bs[2][8][128];

    const int tid  = threadIdx.x;
    const int mblk = blockIdx.y * 128;
    const int nblk = blockIdx.x * 128;

    const int arow = tid >> 1;
    const int kq   = (tid & 1) * 4;

    const float* Aptr;
    if (GATHER) Aptr = A + (size_t)idx[mblk + arow] * K;
    else        Aptr = A + (size_t)(mblk + arow) * K;
    const float* Bptr = Bmat + (size_t)(nblk + arow) * K;

    const int ty = tid >> 4;
    const int tx = tid & 15;

    unsigned long long acc2[8][4];
    #pragma unroll
    for (int i = 0; i < 8; i++)
        #pragma unroll
        for (int p = 0; p < 4; p++) acc2[i][p] = 0ull;

    {
        float4 a4 = *(const float4*)(Aptr + kq);
        float4 b4 = *(const float4*)(Bptr + kq);
        #pragma unroll
        for (int i = 0; i < 4; i++) {
            As[0][kq + i][arow] = ((const float*)&a4)[i];
            Bs[0][kq + i][arow] = ((const float*)&b4)[i];
        }
    }
    __syncthreads();

    const int nkt = K >> 3;
    for (int kt = 0; kt < nkt; kt++) {
        const int cur = kt & 1, nxt = cur ^ 1;
        float4 a4n, b4n;
        const bool more = (kt + 1 < nkt);
        if (more) {
            a4n = *(const float4*)(Aptr + (kt + 1) * 8 + kq);
            b4n = *(const float4*)(Bptr + (kt + 1) * 8 + kq);
        }
        #pragma unroll
        for (int k = 0; k < 8; k++) {
            float af[8];
            *(float4*)&af[0] = *(const float4*)&As[cur][k][ty * 8];
            *(float4*)&af[4] = *(const float4*)&As[cur][k][ty * 8 + 4];
            unsigned long long bp[4];
            const unsigned long long* bq =
                (const unsigned long long*)&Bs[cur][k][tx * 8];
            #pragma unroll
            for (int p = 0; p < 4; p++) bp[p] = bq[p];
            #pragma unroll
            for (int i = 0; i < 8; i++) {
                unsigned long long ad = pack2(af[i], af[i]);
                #pragma unroll
                for (int p = 0; p < 4; p++) ffma2(acc2[i][p], ad, bp[p]);
            }
        }
        if (more) {
            #pragma unroll
            for (int i = 0; i < 4; i++) {
                As[nxt][kq + i][arow] = ((const float*)&a4n)[i];
                Bs[nxt][kq + i][arow] = ((const float*)&b4n)[i];
            }
        }
        __syncthreads();
    }

    float bv[8];
    #pragma unroll
    for (int j = 0; j < 8; j++) bv[j] = bias[nblk + tx * 8 + j];

    #pragma unroll
    for (int i = 0; i < 8; i++) {
        size_t row = (size_t)(mblk + ty * 8 + i);
        float* cp = C + row * (size_t)N + nblk + tx * 8;
        float v[8];
        #pragma unroll
        for (int p = 0; p < 4; p++) {
            float lo, hi;
            unpack2(acc2[i][p], lo, hi);
            v[2 * p]     = lo + bv[2 * p];
            v[2 * p + 1] = hi + bv[2 * p + 1];
        }
        *(float4*)cp       = make_float4(v[0], v[1], v[2], v[3]);
        *(float4*)(cp + 4) = make_float4(v[4], v[5], v[6], v[7]);
    }
}

// ---------------------------------------------------------------------------
// Fused kernel: 136 CTAs x 512 thr, cluster 8 (17 clusters — all wave-1).
// Blocks 0..63  : scan (cluster = batch), R12 body + SMEM-staged xproj
//                 chunks (cp.async double buffer, 128 steps per chunk).
// Blocks 64..135: workers = 2 independent 256-thread half-engines (named
//                 barriers), each = measured standalone logits kernel.
// Tickets: 16000 = 16 chunks x 8 batches x 125 n-tiles (chunk-major).
// ---------------------------------------------------------------------------
#define OP_PITCH   144
#define H_STG      36864              // (128+128) rows * 144B per stage
#define H_BOFF     18432              // B region offset within stage
#define HALF_SMEM  (3 * H_STG)        // 110592 per half
#define FUSED_SMEM (2 * HALF_SMEM)    // 221184
#define NTILES     16000
#define XPBUF_OFF  8192               // scan role: xp chunk buffers
#define XPBUF_SZ   32768              // 128 steps * 64 floats

__global__ __launch_bounds__(512, 1) __cluster_dims__(8, 1, 1)
void fused_scan_logits(const float* __restrict__ xproj,
                       const float* __restrict__ hidden0,
                       const float* __restrict__ W_hh,
                       const float* __restrict__ b_hh,
                       __half* __restrict__ h16,
                       float* __restrict__ hfinal,
                       const __half* __restrict__ Bw,
                       const float* __restrict__ bias,
                       float* __restrict__ C)
{
    extern __shared__ char dsm[];
    __shared__ int sh_tile[2];
    const int tid = threadIdx.x;

    if (blockIdx.x < 64) {
        // ========== SCAN ROLE (R12 body + smem-staged xp chunks) ============
        float* h_buf = (float*)dsm;                  // [2][512]
        float* part  = (float*)(dsm + 4096);         // [8][64]
        char*  xps   = dsm + XPBUF_OFF;              // [2][128][64] floats

        const int batch = blockIdx.x >> 3;
        const int rank  = blockIdx.x & 7;
        const int out   = tid & 63;
        const int kc    = tid >> 6;
        const int kbase = kc * 64;
        const int grow  = rank * 64 + out;

        unsigned long long w2[32];
        {
            const unsigned long long* wq =
                (const unsigned long long*)(W_hh + (size_t)grow * H_ + kbase);
            #pragma unroll
            for (int j = 0; j < 32; j++) w2[j] = wq[j];
        }

        h_buf[tid] = hidden0[batch * H_ + tid];
        const float bhh = (tid < 64) ? b_hh[rank * 64 + tid] : 0.f;

        // xp chunk loader: 32KB per 128-step chunk, 4x16B per thread
        const char* xpc = (const char*)xproj +
                          ((size_t)batch * S_ * H_ + rank * 64) * 4;
        auto load_xp = [&](int c) {
            const uint32_t sb = smem_u32(xps) + (uint32_t)(c & 1) * XPBUF_SZ;
            #pragma unroll
            for (int j = 0; j < 4; j++) {
                int u = tid + 512 * j;
                int s = u >> 4, q = u & 15;
                cp_async16(sb + s * 256 + q * 16,
                           xpc + (size_t)(c * 128 + s) * (H_ * 4) + q * 16);
            }
            CP_COMMIT();
        };
        load_xp(0);

        __syncthreads();
        asm volatile("barrier.cluster.arrive.aligned;" ::: "memory");
        asm volatile("barrier.cluster.wait.aligned;"   ::: "memory");

        __half* hh_b = h16 + (size_t)batch * S_ * H_ + rank * 64;

        float hn = 0.f;
        for (int t = 0; t < S_; t++) {
            const int pb = t & 1;

            // chunk boundary: current chunk's loads complete; prefetch next
            if ((t & 127) == 0) {
                cp_wait<0>();
                __syncthreads();
                const int nc = (t >> 7) + 1;
                if (nc < 16) load_xp(nc);
            }

            float xp = 0.f;
            if (tid < 64)
                xp = *(const float*)(xps + ((t >> 7) & 1) * XPBUF_SZ +
                                     (t & 127) * 256 + tid * 4);

            const unsigned long long* hq =
                (const unsigned long long*)&h_buf[pb * H_ + kbase];
            unsigned long long a0 = 0ull, a1 = 0ull;
            #pragma unroll
            for (int j = 0; j < 16; j++) {
                ffma2(a0, w2[2 * j],     hq[2 * j]);
                ffma2(a1, w2[2 * j + 1], hq[2 * j + 1]);
            }
            float l0, hi0, l1, hi1;
            unpack2(a0, l0, hi0);
            unpack2(a1, l1, hi1);
            part[kc * 64 + out] = (l0 + hi0) + (l1 + hi1);
            __syncthreads();

            if (tid < 64) {
                float s = xp + bhh;
                #pragma unroll
                for (int c = 0; c < 8; c++) s += part[c * 64 + tid];
                hn = tanhf(s);
                hh_b[(size_t)t * H_ + tid] = __float2half(hn);

                uint32_t laddr = smem_u32(&h_buf[(pb ^ 1) * H_ + grow]);
                #pragma unroll
                for (int pr = 0; pr < 8; pr++) {
                    uint32_t paddr;
                    asm("mapa.shared::cluster.u32 %0, %1, %2;"
                        : "=r"(paddr) : "r"(laddr), "r"(pr));
                    asm volatile("st.shared::cluster.f32 [%0], %1;"
                                 :: "r"(paddr), "f"(hn) : "memory");
                }
            }
            __syncthreads();
            asm volatile("barrier.cluster.arrive.aligned;" ::: "memory");
            asm volatile("barrier.cluster.wait.aligned;"   ::: "memory");

            // publish completed 128-step chunk
            if (((t & 127) == 127) && tid == 0) {
                asm volatile("red.release.gpu.global.add.u32 [%0], %1;"
                             :: "l"(&g_progress[batch][t >> 7]), "r"(1u)
                             : "memory");
            }
        }
        if (tid < 64) hfinal[batch * H_ + grow] = hn;
        __syncthreads();   // done with scan smem; fall into worker role
    }

    // ============ WORKER ROLE: two independent 256-thread halves ============
    const __half* Ah = h16;
    const int half = tid >> 8;               // 0 or 1
    const int htid = tid & 255;
    const uint32_t hbase = smem_u32(dsm) + (uint32_t)half * HALF_SMEM;

    const int warp = htid >> 5, lane = htid & 31;
    const int wm = warp & 3;                 // 0..3 (M)
    const int wn = warp >> 2;                // 0..1 (N)

    const int arow = wm * 32 + (lane & 15);
    const int aoff = (lane >> 4) * 16;
    const int nrow = wn * 64 + (lane & 7) + ((lane >> 4) & 1) * 8;
    const int boff = ((lane >> 3) & 1) * 16;

    for (;;) {
        if (htid == 0) sh_tile[half] = (int)atomicAdd(&g_ticket, 1u);
        barh(half);
        const int tile = sh_tile[half];
        barh(half);                            // sh_tile stable before reuse
        if (tile >= NTILES) break;

        // chunk-major 128x128 tile map over 16 chunks of 128 rows
        const int c   = tile / 1000;          // 0..15
        const int rem = tile - c * 1000;
        const int b   = rem / 125;
        const int nt  = rem - b * 125;
        const int mblk = b * S_ + c * 128;
        const int nblk = nt * 128;

        if (htid == 0) {
            unsigned int v;
            for (;;) {
                asm volatile("ld.acquire.gpu.global.u32 %0, [%1];"
                             : "=r"(v) : "l"(&g_progress[b][c]) : "memory");
                if (v >= 8u) break;
                __nanosleep(256);
            }
        }
        barh(half);

        auto load_stage = [&](int kc, int st) {
            const uint32_t sst = hbase + (uint32_t)st * H_STG;
            #pragma unroll
            for (int j = 0; j < 4; j++) {
                int u = htid + 256 * j;
                int row = u >> 3, cc = u & 7;
                cp_async16(sst + row * OP_PITCH + cc * 16,
                           (const char*)Ah +
                           (size_t)(mblk + row) * (H_ * 2) + kc * 128 + cc * 16);
            }
            #pragma unroll
            for (int j = 0; j < 4; j++) {
                int u = htid + 256 * j;
                int row = u >> 3, cc = u & 7;
                cp_async16(sst + H_BOFF + row * OP_PITCH + cc * 16,
                           (const char*)Bw +
                           (size_t)(nblk + row) * (H_ * 2) + kc * 128 + cc * 16);
            }
            CP_COMMIT();
        };

        float acc[2][8][4];
        #pragma unroll
        for (int mi = 0; mi < 2; mi++)
            #pragma unroll
            for (int ni = 0; ni < 8; ni++)
                #pragma unroll
                for (int q = 0; q < 4; q++) acc[mi][ni][q] = 0.f;

        load_stage(0, 0);
        load_stage(1, 1);

        #pragma unroll 1
        for (int kc = 0; kc < 8; kc++) {
            const int st = kc - (kc / 3) * 3;     // kc % 3
            cp_wait<1>();
            barh(half);

            if (kc + 2 < 8) load_stage(kc + 2, (kc + 2) % 3);
            else            CP_COMMIT();          // keep group accounting

            const uint32_t sst = hbase + (uint32_t)st * H_STG;
            const uint32_t ahb = sst;
            const uint32_t bwb = sst + H_BOFF;

            #pragma unroll
            for (int ks = 0; ks < 4; ks++) {
                const int kb = ks * 32;
                uint32_t ah[2][4];
                #pragma unroll
                for (int mi = 0; mi < 2; mi++)
                    ldsm4(ahb + (arow + mi * 16) * OP_PITCH + kb + aoff,
                          ah[mi][0], ah[mi][1], ah[mi][2], ah[mi][3]);
                #pragma unroll
                for (int g = 0; g < 4; g++) {
                    uint32_t bh[4];
                    ldsm4(bwb + (nrow + g * 16) * OP_PITCH + kb + boff,
                          bh[0], bh[1], bh[2], bh[3]);
                    #pragma unroll
                    for (int mi = 0; mi < 2; mi++) {
                        mma_f16(acc[mi][2 * g],
                                ah[mi][0], ah[mi][1], ah[mi][2], ah[mi][3],
                                bh[0], bh[1]);
                        mma_f16(acc[mi][2 * g + 1],
                                ah[mi][0], ah[mi][1], ah[mi][2], ah[mi][3],
                                bh[2], bh[3]);
                    }
                }
            }
        }

        // epilogue
        const int rg = mblk + wm * 32 + (lane >> 2);
        const int cg = nblk + wn * 64 + (lane & 3) * 2;
        #pragma unroll
        for (int mi = 0; mi < 2; mi++) {
            #pragma unroll
            for (int ni = 0; ni < 8; ni++) {
                const int row = rg + mi * 16;
                const int col = cg + ni * 8;
                const float b0 = __ldg(bias + col);
                const float b1 = __ldg(bias + col + 1);
                float2 v0 = make_float2(acc[mi][ni][0] + b0, acc[mi][ni][1] + b1);
                float2 v1 = make_float2(acc[mi][ni][2] + b0, acc[mi][ni][3] + b1);
                *(float2*)(C + (size_t)row * V_ + col)       = v0;
                *(float2*)(C + (size_t)(row + 8) * V_ + col) = v1;
            }
        }
        barh(half);    // epilogue reads done before smem/sh_tile reuse
    }
}

// ---------------------------------------------------------------------------
// Launch
// inputs: 0=x(i32)[B,S] 1=hidden[B,H] 2=embedding[V,E] 3=W_ih[H,E]
//         4=W_hh[H,H] 5=b_ih[H] 6=b_hh[H] 7=W_out[V,H] 8=b_out[V]
// output: logits [B,S,V] then h_final [B,H]
// ---------------------------------------------------------------------------
extern "C" void kernel_launch(void* const* d_in, const int* in_sizes, int n_in,
                              void* d_out, int out_size)
{
    const int*   x         = (const int*)  d_in[0];
    const float* hidden    = (const float*)d_in[1];
    const float* embedding = (const float*)d_in[2];
    const float* W_ih      = (const float*)d_in[3];
    const float* W_hh      = (const float*)d_in[4];
    const float* b_ih      = (const float*)d_in[5];
    const float* b_hh      = (const float*)d_in[6];
    const float* W_out     = (const float*)d_in[7];
    const float* b_out     = (const float*)d_in[8];
    float* out = (float*)d_out;

    float *xproj, *dummy;
    __half *h16, *w16;
    cudaGetSymbolAddress((void**)&xproj, g_xproj);
    cudaGetSymbolAddress((void**)&h16,   g_h16);
    cudaGetSymbolAddress((void**)&w16,   g_w16);
    cudaGetSymbolAddress((void**)&dummy, g_dummy_hf);

    float* hfin = ((long long)out_size >= VOUT + (long long)B_ * H_)
                      ? (out + VOUT) : dummy;

    static bool attr_done = false;
    if (!attr_done) {
        cudaFuncSetAttribute(fused_scan_logits,
                             cudaFuncAttributeMaxDynamicSharedMemorySize,
                             FUSED_SMEM);
        attr_done = true;
    }

    // 0) W_out -> fp16 ; zero overlap flags
    to_half<<<2048, 256>>>(W_out, w16, V_ * H_);
    zero_flags<<<1, 160>>>();

    // 1) x_proj = emb[x] @ W_ih^T + b_ih     [16384,512]  (fp32, full accuracy)
    gemm_nt<true><<<dim3(H_ / 128, MTOT / 128), 256>>>(
        embedding, W_ih, b_ih, xproj, x, MTOT, H_, E_);

    // 2+3) fused: scan (64 CTAs) + overlapped logits GEMM (72x2 half-engines
    //      + full-chip drain)
    fused_scan_logits<<<136, 512, FUSED_SMEM>>>(
        xproj, hidden, W_hh, b_hh, h16, hfin, w16, b_out, out);
}